// round 7
// baseline (speedup 1.0000x reference)
#include <cuda_runtime.h>
#include <cuda_bf16.h>
#include <cstdint>

// Fused SIREN MLP: 3 -> 256 -> 256 -> 256 -> 256 -> 3
// Round 5: weights staged through double-buffered SMEM chunks; mainloop weight
// reads are warp-uniform LDS.128 (true smem broadcast, ~1 wavefront) instead of
// per-thread LDG.128 (~4 wavefronts even when broadcast).  16 neurons per
// inner iteration so activation quads are loaded once per k-step.
// warp = 16 neurons x 64 points, lane = points {l, l+32}, K-packed f32x2.

#define HID 256
#define PTILE 64
#define HROW 260           // smem act row stride (floats); 8-lane phases conflict-free
#define NTHREADS 512
#define KC 16              // k-chunk size (floats per neuron per chunk)
#define NCHUNK (HID / KC)  // 16
#define WCHUNK (HID * KC)  // floats per chunk buffer (4096)

typedef unsigned long long ull;

__device__ __forceinline__ ull fma2(ull a, ull b, ull c) {
    ull d;
    asm("fma.rn.f32x2 %0, %1, %2, %3;" : "=l"(d) : "l"(a), "l"(b), "l"(c));
    return d;
}

// sin for |x| <= pi/2 (+eps); relatively exact at small x by construction
__device__ __forceinline__ float sin_small(float x) {
    float x2 = x * x;
    float p = fmaf(2.7557314e-6f, x2, -1.9841271e-4f);
    p = fmaf(p, x2, 8.3333310e-3f);
    p = fmaf(p, x2, -1.6666667e-1f);
    return fmaf(p * x2, x, x);
}

// accurate sin for |z| <= ~32 via Cody-Waite reduction by pi
__device__ __forceinline__ float sin_cw(float z) {
    float k = rintf(z * 0.318309886183790672f);
    float r = fmaf(k, -3.14159274101257324f, z);
    r = fmaf(k, 8.74227800296169792e-8f, r);
    float s = sin_small(r);
    int ki = (int)k;
    return (ki & 1) ? -s : s;
}

// One hidden layer: GEMM (smem-staged weights) + bias + poly sin.
// hin/hout: [64 pts][HROW].  wbuf: [2][WCHUNK] scratch.
__device__ __forceinline__ void hidden_layer(
    const float* __restrict__ W, const float* __restrict__ b,
    const float* __restrict__ hin, float* __restrict__ hout,
    float* __restrict__ wbuf,
    int ob, int p0, int p1, int tid)
{
    // staging indices: chunk = 256 rows x KC floats = 1024 float4 slots,
    // 2 slots per thread.  slot s -> row o = s>>2, quad q = s&3.
    const int s0 = tid, s1 = tid + NTHREADS;
    const int o0 = s0 >> 2, q0 = (s0 & 3) * 4;
    const int o1 = s1 >> 2, q1 = (s1 & 3) * 4;

    // stage chunk 0 into buffer 0
    {
        float4 v0 = *reinterpret_cast<const float4*>(W + o0 * HID + q0);
        float4 v1 = *reinterpret_cast<const float4*>(W + o1 * HID + q1);
        *reinterpret_cast<float4*>(wbuf + o0 * KC + q0) = v0;
        *reinterpret_cast<float4*>(wbuf + o1 * KC + q1) = v1;
    }

    ull acc[16][2];
#pragma unroll
    for (int j = 0; j < 16; j++) { acc[j][0] = 0ull; acc[j][1] = 0ull; }

    __syncthreads();

#pragma unroll 1
    for (int c = 0; c < NCHUNK; c++) {
        // prefetch next chunk from GMEM early (lands during compute)
        float4 v0, v1;
        if (c + 1 < NCHUNK) {
            const float* Wn = W + (c + 1) * KC;
            v0 = *reinterpret_cast<const float4*>(Wn + o0 * HID + q0);
            v1 = *reinterpret_cast<const float4*>(Wn + o1 * HID + q1);
        }

        const float* wb = wbuf + (c & 1) * WCHUNK + ob * KC;
        const float* h0p = hin + p0 * HROW + c * KC;
        const float* h1p = hin + p1 * HROW + c * KC;

#pragma unroll
        for (int kb = 0; kb < KC; kb += 4) {
            ulonglong2 h0 = *reinterpret_cast<const ulonglong2*>(h0p + kb);
            ulonglong2 h1 = *reinterpret_cast<const ulonglong2*>(h1p + kb);
#pragma unroll
            for (int j = 0; j < 16; j++) {
                // warp-uniform address -> smem broadcast
                ulonglong2 wq = *reinterpret_cast<const ulonglong2*>(
                    wb + j * KC + kb);
                acc[j][0] = fma2(wq.x, h0.x, acc[j][0]);
                acc[j][1] = fma2(wq.x, h1.x, acc[j][1]);
                acc[j][0] = fma2(wq.y, h0.y, acc[j][0]);
                acc[j][1] = fma2(wq.y, h1.y, acc[j][1]);
            }
        }

        if (c + 1 < NCHUNK) {
            float* wn = wbuf + ((c + 1) & 1) * WCHUNK;
            *reinterpret_cast<float4*>(wn + o0 * KC + q0) = v0;
            *reinterpret_cast<float4*>(wn + o1 * KC + q1) = v1;
        }
        __syncthreads();
    }

    // epilogue: fold even/odd-k partials, bias, poly sin, store transposed
#pragma unroll
    for (int j = 0; j < 16; j++) {
        int o = ob + j;
        float bb = __ldg(b + o);
        float2 a0 = *reinterpret_cast<float2*>(&acc[j][0]);
        float2 a1 = *reinterpret_cast<float2*>(&acc[j][1]);
        hout[p0 * HROW + o] = sin_small(a0.x + a0.y + bb);
        hout[p1 * HROW + o] = sin_small(a1.x + a1.y + bb);
    }
}

__global__ void __launch_bounds__(NTHREADS, 1) siren_fused_kernel(
    const float* __restrict__ x,
    const float* __restrict__ W0, const float* __restrict__ b0,
    const float* __restrict__ W1, const float* __restrict__ b1,
    const float* __restrict__ W2, const float* __restrict__ b2,
    const float* __restrict__ W3, const float* __restrict__ b3,
    const float* __restrict__ W4, const float* __restrict__ b4,
    float* __restrict__ out, int npts)
{
    extern __shared__ float sm[];
    float* hA   = sm;                          // [64][HROW]
    float* hB   = sm + PTILE * HROW;           // [64][HROW]
    float* wbuf = sm + 2 * PTILE * HROW;       // [2][WCHUNK]
    float* xs   = wbuf + 2 * WCHUNK;           // [64*3]

    const int tid = threadIdx.x;
    const int w = tid >> 5;
    const int l = tid & 31;
    const int p0 = l;
    const int p1 = l + 32;
    const int ob = w * 16;                     // 16 neurons per warp
    const int tile0 = blockIdx.x * PTILE;

    // stage x tile (64 points x 3)
    if (tid < PTILE * 3) {
        int idx = tile0 * 3 + tid;
        xs[tid] = (idx < npts * 3) ? x[idx] : 0.0f;
    }
    __syncthreads();

    // ---- layer 0: h0[p][o] = sin(30*(W0 x + b0)), accurate sin ----
    {
        float xa0 = xs[p0 * 3 + 0], xa1 = xs[p0 * 3 + 1], xa2 = xs[p0 * 3 + 2];
        float xb0 = xs[p1 * 3 + 0], xb1 = xs[p1 * 3 + 1], xb2 = xs[p1 * 3 + 2];
#pragma unroll
        for (int n = 0; n < 16; n++) {
            int o = ob + n;
            float w0 = __ldg(W0 + 3 * o + 0);
            float w1 = __ldg(W0 + 3 * o + 1);
            float w2 = __ldg(W0 + 3 * o + 2);
            float bb = __ldg(b0 + o);
            float za = 30.0f * fmaf(w0, xa0, fmaf(w1, xa1, fmaf(w2, xa2, bb)));
            float zb = 30.0f * fmaf(w0, xb0, fmaf(w1, xb1, fmaf(w2, xb2, bb)));
            hA[p0 * HROW + o] = sin_cw(za);
            hA[p1 * HROW + o] = sin_cw(zb);
        }
    }
    __syncthreads();

    // ---- hidden layers ----
    hidden_layer(W1, b1, hA, hB, wbuf, ob, p0, p1, tid);
    __syncthreads();
    hidden_layer(W2, b2, hB, hA, wbuf, ob, p0, p1, tid);
    __syncthreads();
    hidden_layer(W3, b3, hA, hB, wbuf, ob, p0, p1, tid);
    __syncthreads();

    // ---- layer 4: out[p][c] = W4[c] . h3[p][:] + b4[c]  (reads hB) ----
    if (tid < PTILE * 3) {
        int c = tid >> 6;            // 0..2 (uniform per warp)
        int p = tid & 63;
        const float* hrow = hB + p * HROW;
        const float* wrow = W4 + c * HID;
        ull acc0 = 0ull, acc1 = 0ull;
#pragma unroll 8
        for (int kb = 0; kb < HID; kb += 4) {
            ulonglong2 hq = *reinterpret_cast<const ulonglong2*>(hrow + kb);
            ulonglong2 wq = *reinterpret_cast<const ulonglong2*>(wrow + kb);
            acc0 = fma2(wq.x, hq.x, acc0);
            acc1 = fma2(wq.y, hq.y, acc1);
        }
        float2 a0 = *reinterpret_cast<float2*>(&acc0);
        float2 a1 = *reinterpret_cast<float2*>(&acc1);
        float v = a0.x + a0.y + a1.x + a1.y + __ldg(b4 + c);
        int prow = tile0 + p;
        if (prow < npts) out[prow * 3 + c] = v;
    }
}

extern "C" void kernel_launch(void* const* d_in, const int* in_sizes, int n_in,
                              void* d_out, int out_size) {
    const float* x  = (const float*)d_in[0];
    const float* W0 = (const float*)d_in[1];
    const float* b0 = (const float*)d_in[2];
    const float* W1 = (const float*)d_in[3];
    const float* b1 = (const float*)d_in[4];
    const float* W2 = (const float*)d_in[5];
    const float* b2 = (const float*)d_in[6];
    const float* W3 = (const float*)d_in[7];
    const float* b3 = (const float*)d_in[8];
    const float* W4 = (const float*)d_in[9];
    const float* b4 = (const float*)d_in[10];
    float* out = (float*)d_out;

    int npts = in_sizes[0] / 3;
    int nblocks = (npts + PTILE - 1) / PTILE;

    // 2*64*260 + 2*4096 + 192 floats = 166,400 B
    size_t smem = (2 * PTILE * HROW + 2 * WCHUNK + PTILE * 3) * sizeof(float);
    cudaFuncSetAttribute(siren_fused_kernel,
                         cudaFuncAttributeMaxDynamicSharedMemorySize,
                         (int)smem);

    siren_fused_kernel<<<nblocks, NTHREADS, smem>>>(
        x, W0, b0, W1, b1, W2, b2, W3, b3, W4, b4, out, npts);
}

// round 8
// speedup vs baseline: 1.1632x; 1.1632x over previous
#include <cuda_runtime.h>
#include <cuda_bf16.h>
#include <cstdint>

// Fused SIREN MLP: 3 -> 256 -> 256 -> 256 -> 256 -> 3
// Round 6: per-warp private weight staging (each warp stages only its own 16
// neuron rows into its own double-buffered smem region) -> NO block barriers
// in the GEMM mainloop, only __syncwarp per chunk.  KC=32 (8 chunks/layer).
// warp = 16 neurons x 64 points, lane = points {l, l+32}, K-packed f32x2.

#define HID 256
#define PTILE 64
#define HROW 260           // smem act row stride (floats)
#define NTHREADS 512
#define KC 32              // k-chunk size
#define NCHUNK (HID / KC)  // 8
#define WROWS 16           // neuron rows per warp
#define WBUF_HALF (WROWS * KC)        // 512 floats
#define WBUF_PER (2 * WBUF_HALF)      // 1024 floats per warp

typedef unsigned long long ull;

__device__ __forceinline__ ull fma2(ull a, ull b, ull c) {
    ull d;
    asm("fma.rn.f32x2 %0, %1, %2, %3;" : "=l"(d) : "l"(a), "l"(b), "l"(c));
    return d;
}

// sin for |x| <= pi/2 (+eps); relatively exact at small x by construction
__device__ __forceinline__ float sin_small(float x) {
    float x2 = x * x;
    float p = fmaf(2.7557314e-6f, x2, -1.9841271e-4f);
    p = fmaf(p, x2, 8.3333310e-3f);
    p = fmaf(p, x2, -1.6666667e-1f);
    return fmaf(p * x2, x, x);
}

// accurate sin for |z| <= ~32 via Cody-Waite reduction by pi
__device__ __forceinline__ float sin_cw(float z) {
    float k = rintf(z * 0.318309886183790672f);
    float r = fmaf(k, -3.14159274101257324f, z);
    r = fmaf(k, 8.74227800296169792e-8f, r);
    float s = sin_small(r);
    int ki = (int)k;
    return (ki & 1) ? -s : s;
}

// One hidden layer.  hin/hout: [64 pts][HROW].  wbuf_w: this warp's private
// [2][WROWS*KC] staging region.  Warp owns neurons [ob, ob+16), lane owns
// points p0=l, p1=l+32.  Staging: lane slots s in {l,l+32,l+64,l+96}:
// row j = s>>3, quad q = (s&7)*4   (16 rows x 32 floats = 128 float4).
__device__ __forceinline__ void hidden_layer(
    const float* __restrict__ W, const float* __restrict__ b,
    const float* __restrict__ hin, float* __restrict__ hout,
    float* __restrict__ wbuf_w,
    int ob, int p0, int p1, int lane)
{
    const int j0 = lane >> 3,             q0 = (lane & 7) * 4;
    const int j1 = (lane + 32) >> 3,      q1 = q0;
    const int j2 = (lane + 64) >> 3,      q2 = q0;
    const int j3 = (lane + 96) >> 3,      q3 = q0;
    const float* Wb = W + ob * HID;

    // stage chunk 0 into buffer 0
    {
        float4 v0 = *reinterpret_cast<const float4*>(Wb + j0 * HID + q0);
        float4 v1 = *reinterpret_cast<const float4*>(Wb + j1 * HID + q1);
        float4 v2 = *reinterpret_cast<const float4*>(Wb + j2 * HID + q2);
        float4 v3 = *reinterpret_cast<const float4*>(Wb + j3 * HID + q3);
        *reinterpret_cast<float4*>(wbuf_w + j0 * KC + q0) = v0;
        *reinterpret_cast<float4*>(wbuf_w + j1 * KC + q1) = v1;
        *reinterpret_cast<float4*>(wbuf_w + j2 * KC + q2) = v2;
        *reinterpret_cast<float4*>(wbuf_w + j3 * KC + q3) = v3;
    }
    __syncwarp();

    ull acc[16][2];
#pragma unroll
    for (int j = 0; j < 16; j++) { acc[j][0] = 0ull; acc[j][1] = 0ull; }

#pragma unroll 1
    for (int c = 0; c < NCHUNK; c++) {
        // prefetch next chunk (lands during this chunk's compute)
        float4 v0, v1, v2, v3;
        if (c + 1 < NCHUNK) {
            const float* Wn = Wb + (c + 1) * KC;
            v0 = *reinterpret_cast<const float4*>(Wn + j0 * HID + q0);
            v1 = *reinterpret_cast<const float4*>(Wn + j1 * HID + q1);
            v2 = *reinterpret_cast<const float4*>(Wn + j2 * HID + q2);
            v3 = *reinterpret_cast<const float4*>(Wn + j3 * HID + q3);
        }

        const float* wb = wbuf_w + (c & 1) * WBUF_HALF;
        const float* h0p = hin + p0 * HROW + c * KC;
        const float* h1p = hin + p1 * HROW + c * KC;

#pragma unroll
        for (int kb = 0; kb < KC; kb += 4) {
            ulonglong2 h0 = *reinterpret_cast<const ulonglong2*>(h0p + kb);
            ulonglong2 h1 = *reinterpret_cast<const ulonglong2*>(h1p + kb);
#pragma unroll
            for (int j = 0; j < 16; j++) {
                // warp-uniform address -> smem broadcast
                ulonglong2 wq = *reinterpret_cast<const ulonglong2*>(
                    wb + j * KC + kb);
                acc[j][0] = fma2(wq.x, h0.x, acc[j][0]);
                acc[j][1] = fma2(wq.x, h1.x, acc[j][1]);
                acc[j][0] = fma2(wq.y, h0.y, acc[j][0]);
                acc[j][1] = fma2(wq.y, h1.y, acc[j][1]);
            }
        }

        if (c + 1 < NCHUNK) {
            float* wn = wbuf_w + ((c + 1) & 1) * WBUF_HALF;
            *reinterpret_cast<float4*>(wn + j0 * KC + q0) = v0;
            *reinterpret_cast<float4*>(wn + j1 * KC + q1) = v1;
            *reinterpret_cast<float4*>(wn + j2 * KC + q2) = v2;
            *reinterpret_cast<float4*>(wn + j3 * KC + q3) = v3;
        }
        __syncwarp();
    }

    // epilogue: fold partials, bias, poly sin, paired STS.64 stores
#pragma unroll
    for (int j = 0; j < 16; j += 2) {
        int o = ob + j;
        float bbx = __ldg(b + o);
        float bby = __ldg(b + o + 1);
        float2 a00 = *reinterpret_cast<float2*>(&acc[j][0]);
        float2 a01 = *reinterpret_cast<float2*>(&acc[j][1]);
        float2 a10 = *reinterpret_cast<float2*>(&acc[j + 1][0]);
        float2 a11 = *reinterpret_cast<float2*>(&acc[j + 1][1]);
        float s0x = sin_small(a00.x + a00.y + bbx);
        float s0y = sin_small(a10.x + a10.y + bby);
        float s1x = sin_small(a01.x + a01.y + bbx);
        float s1y = sin_small(a11.x + a11.y + bby);
        *reinterpret_cast<float2*>(hout + p0 * HROW + o) = make_float2(s0x, s0y);
        *reinterpret_cast<float2*>(hout + p1 * HROW + o) = make_float2(s1x, s1y);
    }
}

__global__ void __launch_bounds__(NTHREADS, 1) siren_fused_kernel(
    const float* __restrict__ x,
    const float* __restrict__ W0, const float* __restrict__ b0,
    const float* __restrict__ W1, const float* __restrict__ b1,
    const float* __restrict__ W2, const float* __restrict__ b2,
    const float* __restrict__ W3, const float* __restrict__ b3,
    const float* __restrict__ W4, const float* __restrict__ b4,
    float* __restrict__ out, int npts)
{
    extern __shared__ float sm[];
    float* hA   = sm;                          // [64][HROW]
    float* hB   = sm + PTILE * HROW;           // [64][HROW]
    float* wbuf = sm + 2 * PTILE * HROW;       // [16 warps][WBUF_PER]
    float* xs   = wbuf + 16 * WBUF_PER;        // [64*3]

    const int tid = threadIdx.x;
    const int w = tid >> 5;
    const int l = tid & 31;
    const int p0 = l;
    const int p1 = l + 32;
    const int ob = w * 16;                     // 16 neurons per warp
    const int tile0 = blockIdx.x * PTILE;
    float* wbuf_w = wbuf + w * WBUF_PER;

    // stage x tile (64 points x 3)
    if (tid < PTILE * 3) {
        int idx = tile0 * 3 + tid;
        xs[tid] = (idx < npts * 3) ? x[idx] : 0.0f;
    }
    __syncthreads();

    // ---- layer 0: h0[p][o] = sin(30*(W0 x + b0)), accurate sin ----
    {
        float xa0 = xs[p0 * 3 + 0], xa1 = xs[p0 * 3 + 1], xa2 = xs[p0 * 3 + 2];
        float xb0 = xs[p1 * 3 + 0], xb1 = xs[p1 * 3 + 1], xb2 = xs[p1 * 3 + 2];
#pragma unroll
        for (int n = 0; n < 16; n++) {
            int o = ob + n;
            float w0 = __ldg(W0 + 3 * o + 0);
            float w1 = __ldg(W0 + 3 * o + 1);
            float w2 = __ldg(W0 + 3 * o + 2);
            float bb = __ldg(b0 + o);
            float za = 30.0f * fmaf(w0, xa0, fmaf(w1, xa1, fmaf(w2, xa2, bb)));
            float zb = 30.0f * fmaf(w0, xb0, fmaf(w1, xb1, fmaf(w2, xb2, bb)));
            hA[p0 * HROW + o] = sin_cw(za);
            hA[p1 * HROW + o] = sin_cw(zb);
        }
    }
    __syncthreads();

    // ---- hidden layers (no block barriers inside) ----
    hidden_layer(W1, b1, hA, hB, wbuf_w, ob, p0, p1, l);
    __syncthreads();
    hidden_layer(W2, b2, hB, hA, wbuf_w, ob, p0, p1, l);
    __syncthreads();
    hidden_layer(W3, b3, hA, hB, wbuf_w, ob, p0, p1, l);
    __syncthreads();

    // ---- layer 4: out[p][c] = W4[c] . h3[p][:] + b4[c]  (reads hB) ----
    if (tid < PTILE * 3) {
        int c = tid >> 6;            // 0..2 (uniform per warp)
        int p = tid & 63;
        const float* hrow = hB + p * HROW;
        const float* wrow = W4 + c * HID;
        ull acc0 = 0ull, acc1 = 0ull;
#pragma unroll 8
        for (int kb = 0; kb < HID; kb += 4) {
            ulonglong2 hq = *reinterpret_cast<const ulonglong2*>(hrow + kb);
            ulonglong2 wq = *reinterpret_cast<const ulonglong2*>(wrow + kb);
            acc0 = fma2(wq.x, hq.x, acc0);
            acc1 = fma2(wq.y, hq.y, acc1);
        }
        float2 a0 = *reinterpret_cast<float2*>(&acc0);
        float2 a1 = *reinterpret_cast<float2*>(&acc1);
        float v = a0.x + a0.y + a1.x + a1.y + __ldg(b4 + c);
        int prow = tile0 + p;
        if (prow < npts) out[prow * 3 + c] = v;
    }
}

extern "C" void kernel_launch(void* const* d_in, const int* in_sizes, int n_in,
                              void* d_out, int out_size) {
    const float* x  = (const float*)d_in[0];
    const float* W0 = (const float*)d_in[1];
    const float* b0 = (const float*)d_in[2];
    const float* W1 = (const float*)d_in[3];
    const float* b1 = (const float*)d_in[4];
    const float* W2 = (const float*)d_in[5];
    const float* b2 = (const float*)d_in[6];
    const float* W3 = (const float*)d_in[7];
    const float* b3 = (const float*)d_in[8];
    const float* W4 = (const float*)d_in[9];
    const float* b4 = (const float*)d_in[10];
    float* out = (float*)d_out;

    int npts = in_sizes[0] / 3;
    int nblocks = (npts + PTILE - 1) / PTILE;

    // acts 133,120 B + weights 65,536 B + xs 768 B = 199,424 B
    size_t smem = (2 * PTILE * HROW + 16 * WBUF_PER + PTILE * 3) * sizeof(float);
    cudaFuncSetAttribute(siren_fused_kernel,
                         cudaFuncAttributeMaxDynamicSharedMemorySize,
                         (int)smem);

    siren_fused_kernel<<<nblocks, NTHREADS, smem>>>(
        x, W0, b0, W1, b1, W2, b2, W3, b3, W4, b4, out, npts);
}

// round 10
// speedup vs baseline: 2.6258x; 2.2574x over previous
#include <cuda_runtime.h>
#include <cuda_bf16.h>
#include <cstdint>

// Fused SIREN MLP via warp-level bf16 HMMA (mma.sync.m16n8k16 — baseline PTX,
// no sm_103a-only features):  3 -> 256 -> 256 -> 256 -> 256 -> 3
// CTA = 128 points, 16 warps (4 M-groups x 4 N-groups), warp tile 32p x 64n.
// Split-bf16: A = Ahi+Alo, W = Whi+Wlo; D = Ahi*Whi + Alo*Whi + Ahi*Wlo (f32 acc).
// Acts in SMEM [p][k] bf16 hi/lo (row 528B, ldmatrix conflict-free), updated
// in place per layer.  Weights staged fp32->bf16 hi/lo per 32-k chunk,
// double-buffered around the chunk's MMAs.

#define NTHREADS 512
#define PTILE 128
#define HID 256
#define KC 32
#define NCHUNK 8
#define AROWB 528          // bytes per A row (264 bf16): 132 words, stride 4 banks
#define BROWB 80           // bytes per B row (40 bf16): 20 words, conflict-free

#define A_HALF   67584     // 128 * 528
#define OFF_ALO  67584
#define OFF_B    135168
#define B_HALF   20480     // 256 * 80
#define B_BUF    40960
#define OFF_PSUM 217088    // [4][128][3] f32 = 6144 B
#define OFF_XS   223232    // 128*3 f32
#define SMEM_SZ  224768

__device__ __forceinline__ uint32_t smem_u32(const void* p) {
    uint32_t a;
    asm("{ .reg .u64 t; cvta.to.shared.u64 t, %1; cvt.u32.u64 %0, t; }"
        : "=r"(a) : "l"(p));
    return a;
}

__device__ __forceinline__ void ldsm4(uint32_t a[4], uint32_t addr) {
    asm volatile("ldmatrix.sync.aligned.m8n8.x4.shared.b16 {%0,%1,%2,%3}, [%4];"
                 : "=r"(a[0]), "=r"(a[1]), "=r"(a[2]), "=r"(a[3]) : "r"(addr));
}

__device__ __forceinline__ void mma16816(float d[4], const uint32_t a[4],
                                         uint32_t b0, uint32_t b1) {
    asm volatile("mma.sync.aligned.m16n8k16.row.col.f32.bf16.bf16.f32 "
                 "{%0,%1,%2,%3}, {%4,%5,%6,%7}, {%8,%9}, {%0,%1,%2,%3};"
                 : "+f"(d[0]), "+f"(d[1]), "+f"(d[2]), "+f"(d[3])
                 : "r"(a[0]), "r"(a[1]), "r"(a[2]), "r"(a[3]),
                   "r"(b0), "r"(b1));
}

// pack two fp32 -> bf16x2 (v0 low), and hi/lo split
__device__ __forceinline__ uint32_t packbf(float v0, float v1) {
    uint32_t r;
    asm("cvt.rn.bf16x2.f32 %0, %1, %2;" : "=r"(r) : "f"(v1), "f"(v0));
    return r;
}
__device__ __forceinline__ void split2(float s0, float s1,
                                       uint32_t& hi, uint32_t& lo) {
    hi = packbf(s0, s1);
    float h0 = __uint_as_float(hi << 16);
    float h1 = __uint_as_float(hi & 0xffff0000u);
    lo = packbf(s0 - h0, s1 - h1);
}

__device__ __forceinline__ float sin_small(float x) {   // |x| <= ~pi/2
    float x2 = x * x;
    float p = fmaf(2.7557314e-6f, x2, -1.9841271e-4f);
    p = fmaf(p, x2, 8.3333310e-3f);
    p = fmaf(p, x2, -1.6666667e-1f);
    return fmaf(p * x2, x, x);
}
__device__ __forceinline__ float sin_cw(float z) {      // |z| <= ~32
    float k = rintf(z * 0.318309886183790672f);
    float r = fmaf(k, -3.14159274101257324f, z);
    r = fmaf(k, 8.74227800296169792e-8f, r);
    float s = sin_small(r);
    return (((int)k) & 1) ? -s : s;
}

__global__ void __launch_bounds__(NTHREADS, 1) siren_mma_kernel(
    const float* __restrict__ x,
    const float* __restrict__ W0, const float* __restrict__ b0,
    const float* __restrict__ W1, const float* __restrict__ b1,
    const float* __restrict__ W2, const float* __restrict__ b2,
    const float* __restrict__ W3, const float* __restrict__ b3,
    const float* __restrict__ W4, const float* __restrict__ b4,
    float* __restrict__ out, int npts)
{
    extern __shared__ char smem[];
    const uint32_t sb = smem_u32(smem);
    const int tid = threadIdx.x;
    const int w = tid >> 5, l = tid & 31;
    const int mw = w & 3, nw = w >> 2;
    const int tile0 = blockIdx.x * PTILE;

    float* xs = (float*)(smem + OFF_XS);
    float* psum = (float*)(smem + OFF_PSUM);

    if (tid < PTILE * 3) {
        int idx = tile0 * 3 + tid;
        xs[tid] = (idx < npts * 3) ? x[idx] : 0.0f;
    }
    __syncthreads();

    // ---- layer 0: h0 = sin(30*(W0 x + b0)) -> A hi/lo (fp32-accurate) ----
    {
        int p = tid >> 2;
        int nb = (tid & 3) * 64;
        float x0 = xs[p * 3], x1 = xs[p * 3 + 1], x2 = xs[p * 3 + 2];
        char* ahr = smem + p * AROWB;
        char* alr = smem + OFF_ALO + p * AROWB;
#pragma unroll 8
        for (int j = 0; j < 64; j += 2) {
            int n = nb + j;
            float za = 30.0f * fmaf(__ldg(W0 + n * 3), x0,
                           fmaf(__ldg(W0 + n * 3 + 1), x1,
                           fmaf(__ldg(W0 + n * 3 + 2), x2, __ldg(b0 + n))));
            float zb = 30.0f * fmaf(__ldg(W0 + n * 3 + 3), x0,
                           fmaf(__ldg(W0 + n * 3 + 4), x1,
                           fmaf(__ldg(W0 + n * 3 + 5), x2, __ldg(b0 + n + 1))));
            uint32_t hi, lo;
            split2(sin_cw(za), sin_cw(zb), hi, lo);
            *(uint32_t*)(ahr + n * 2) = hi;
            *(uint32_t*)(alr + n * 2) = lo;
        }
    }
    __syncthreads();

    // ---- ldmatrix per-lane address components ----
    const int lt = l >> 3, l7 = l & 7;
    // A tiles: t0:(r,k0) t1:(r+8,k0) t2:(r,k8) t3:(r+8,k8)
    const uint32_t aBase = sb + (uint32_t)((mw * 32 + l7 + ((lt & 1) << 3)) * AROWB
                                           + (((lt >> 1) << 3) * 2));
    // B tiles: t0:(n,k0) t1:(n,k8) t2:(n+8,k0) t3:(n+8,k8)
    const uint32_t bBase = sb + OFF_B
        + (uint32_t)((nw * 64 + l7 + ((lt >> 1) << 3)) * BROWB
                     + (((lt & 1) << 3) * 2));

    // staging indices: thread -> (n = tid/2, k-half = (tid&1)*16)
    const int sn = tid >> 1;
    const int skh = (tid & 1) << 4;

    // ---- 3 hidden GEMM layers (last one folds the 256->3 output) ----
#pragma unroll 1
    for (int L = 0; L < 3; L++) {
        const float* W = (L == 0) ? W1 : (L == 1) ? W2 : W3;
        const float* bb = (L == 0) ? b1 : (L == 1) ? b2 : b3;

        float acc[2][8][4];
#pragma unroll
        for (int mt = 0; mt < 2; mt++)
#pragma unroll
            for (int nt = 0; nt < 8; nt++)
#pragma unroll
                for (int q = 0; q < 4; q++) acc[mt][nt][q] = 0.0f;

        // stage chunk 0
        {
            const float* src = W + sn * HID + skh;
            float4 f0 = *(const float4*)(src);
            float4 f1 = *(const float4*)(src + 4);
            float4 f2 = *(const float4*)(src + 8);
            float4 f3 = *(const float4*)(src + 12);
            float v[16] = {f0.x, f0.y, f0.z, f0.w, f1.x, f1.y, f1.z, f1.w,
                           f2.x, f2.y, f2.z, f2.w, f3.x, f3.y, f3.z, f3.w};
            uint32_t hi[8], lo[8];
#pragma unroll
            for (int t = 0; t < 8; t++) split2(v[2 * t], v[2 * t + 1], hi[t], lo[t]);
            char* dh = smem + OFF_B + sn * BROWB + skh * 2;
            *(uint4*)dh        = make_uint4(hi[0], hi[1], hi[2], hi[3]);
            *(uint4*)(dh + 16) = make_uint4(hi[4], hi[5], hi[6], hi[7]);
            char* dl = dh + B_HALF;
            *(uint4*)dl        = make_uint4(lo[0], lo[1], lo[2], lo[3]);
            *(uint4*)(dl + 16) = make_uint4(lo[4], lo[5], lo[6], lo[7]);
        }
        __syncthreads();

#pragma unroll 1
        for (int c = 0; c < NCHUNK; c++) {
            // prefetch next chunk from GMEM (lands during MMA)
            float4 g0, g1, g2, g3;
            if (c + 1 < NCHUNK) {
                const float* src = W + sn * HID + (c + 1) * KC + skh;
                g0 = *(const float4*)(src);
                g1 = *(const float4*)(src + 4);
                g2 = *(const float4*)(src + 8);
                g3 = *(const float4*)(src + 12);
            }
            const uint32_t bufB = bBase + (uint32_t)((c & 1) * B_BUF);

#pragma unroll
            for (int s = 0; s < 2; s++) {
                const int kk = c * 2 + s;
                uint32_t ahi[2][4], alo[2][4];
                ldsm4(ahi[0], aBase + kk * 32);
                ldsm4(ahi[1], aBase + 16 * AROWB + kk * 32);
                ldsm4(alo[0], aBase + A_HALF + kk * 32);
                ldsm4(alo[1], aBase + A_HALF + 16 * AROWB + kk * 32);
#pragma unroll
                for (int np = 0; np < 4; np++) {
                    uint32_t bh[4], bl[4];
                    uint32_t ba = bufB + np * 16 * BROWB + s * 32;
                    ldsm4(bh, ba);
                    ldsm4(bl, ba + B_HALF);
#pragma unroll
                    for (int mt = 0; mt < 2; mt++) {
                        mma16816(acc[mt][2 * np],     ahi[mt], bh[0], bh[1]);
                        mma16816(acc[mt][2 * np],     alo[mt], bh[0], bh[1]);
                        mma16816(acc[mt][2 * np],     ahi[mt], bl[0], bl[1]);
                        mma16816(acc[mt][2 * np + 1], ahi[mt], bh[2], bh[3]);
                        mma16816(acc[mt][2 * np + 1], alo[mt], bh[2], bh[3]);
                        mma16816(acc[mt][2 * np + 1], ahi[mt], bl[2], bl[3]);
                    }
                }
            }

            if (c + 1 < NCHUNK) {
                float v[16] = {g0.x, g0.y, g0.z, g0.w, g1.x, g1.y, g1.z, g1.w,
                               g2.x, g2.y, g2.z, g2.w, g3.x, g3.y, g3.z, g3.w};
                uint32_t hi[8], lo[8];
#pragma unroll
                for (int t = 0; t < 8; t++)
                    split2(v[2 * t], v[2 * t + 1], hi[t], lo[t]);
                char* dh = smem + OFF_B + ((c + 1) & 1) * B_BUF
                         + sn * BROWB + skh * 2;
                *(uint4*)dh        = make_uint4(hi[0], hi[1], hi[2], hi[3]);
                *(uint4*)(dh + 16) = make_uint4(hi[4], hi[5], hi[6], hi[7]);
                char* dl = dh + B_HALF;
                *(uint4*)dl        = make_uint4(lo[0], lo[1], lo[2], lo[3]);
                *(uint4*)(dl + 16) = make_uint4(lo[4], lo[5], lo[6], lo[7]);
            }
            __syncthreads();   // staging visible; all A reads of this layer done by c=7
        }

        if (L < 2) {
            // epilogue: sin(D + b) -> split bf16 -> A (in place), then barrier
#pragma unroll
            for (int mt = 0; mt < 2; mt++) {
                int pr = mw * 32 + mt * 16 + (l >> 2);
#pragma unroll
                for (int nt = 0; nt < 8; nt++) {
                    int nc = nw * 64 + nt * 8 + (l & 3) * 2;
                    float bn0 = __ldg(bb + nc), bn1 = __ldg(bb + nc + 1);
                    float s0 = sin_small(acc[mt][nt][0] + bn0);
                    float s1 = sin_small(acc[mt][nt][1] + bn1);
                    float s2 = sin_small(acc[mt][nt][2] + bn0);
                    float s3 = sin_small(acc[mt][nt][3] + bn1);
                    uint32_t h01, l01, h23, l23;
                    split2(s0, s1, h01, l01);
                    split2(s2, s3, h23, l23);
                    *(uint32_t*)(smem + pr * AROWB + nc * 2)                 = h01;
                    *(uint32_t*)(smem + OFF_ALO + pr * AROWB + nc * 2)       = l01;
                    *(uint32_t*)(smem + (pr + 8) * AROWB + nc * 2)           = h23;
                    *(uint32_t*)(smem + OFF_ALO + (pr + 8) * AROWB + nc * 2) = l23;
                }
            }
            __syncthreads();
        } else {
            // final: h3 = sin(D + b3); partial out_c = sum_n W4[c][n]*h3[n]
            float part[2][2][3];
#pragma unroll
            for (int mt = 0; mt < 2; mt++)
#pragma unroll
                for (int rh = 0; rh < 2; rh++)
#pragma unroll
                    for (int cc = 0; cc < 3; cc++) part[mt][rh][cc] = 0.0f;

#pragma unroll
            for (int mt = 0; mt < 2; mt++)
#pragma unroll
            for (int nt = 0; nt < 8; nt++) {
                int nc = nw * 64 + nt * 8 + (l & 3) * 2;
                float bn0 = __ldg(bb + nc), bn1 = __ldg(bb + nc + 1);
                float h0 = sin_small(acc[mt][nt][0] + bn0);
                float h1 = sin_small(acc[mt][nt][1] + bn1);
                float h2 = sin_small(acc[mt][nt][2] + bn0);
                float h3v = sin_small(acc[mt][nt][3] + bn1);
#pragma unroll
                for (int cc = 0; cc < 3; cc++) {
                    float w0v = __ldg(W4 + cc * HID + nc);
                    float w1v = __ldg(W4 + cc * HID + nc + 1);
                    part[mt][0][cc] = fmaf(w0v, h0, fmaf(w1v, h1, part[mt][0][cc]));
                    part[mt][1][cc] = fmaf(w0v, h2, fmaf(w1v, h3v, part[mt][1][cc]));
                }
            }
            // reduce across the 4 lanes sharing each point (lane%4)
#pragma unroll
            for (int mt = 0; mt < 2; mt++)
#pragma unroll
            for (int rh = 0; rh < 2; rh++)
#pragma unroll
            for (int cc = 0; cc < 3; cc++) {
                float v = part[mt][rh][cc];
                v += __shfl_xor_sync(0xffffffffu, v, 1);
                v += __shfl_xor_sync(0xffffffffu, v, 2);
                part[mt][rh][cc] = v;
            }
            if ((l & 3) == 0) {
#pragma unroll
                for (int mt = 0; mt < 2; mt++)
#pragma unroll
                for (int rh = 0; rh < 2; rh++) {
                    int p = mw * 32 + mt * 16 + rh * 8 + (l >> 2);
#pragma unroll
                    for (int cc = 0; cc < 3; cc++)
                        psum[nw * 384 + p * 3 + cc] = part[mt][rh][cc];
                }
            }
        }
    }

    __syncthreads();
    if (tid < 384) {
        float v = psum[tid] + psum[384 + tid] + psum[768 + tid]
                + psum[1152 + tid] + __ldg(b4 + tid % 3);
        int idx = tile0 * 3 + tid;
        if (idx < npts * 3) out[idx] = v;
    }
}

extern "C" void kernel_launch(void* const* d_in, const int* in_sizes, int n_in,
                              void* d_out, int out_size) {
    const float* x  = (const float*)d_in[0];
    const float* W0 = (const float*)d_in[1];
    const float* b0 = (const float*)d_in[2];
    const float* W1 = (const float*)d_in[3];
    const float* b1 = (const float*)d_in[4];
    const float* W2 = (const float*)d_in[5];
    const float* b2 = (const float*)d_in[6];
    const float* W3 = (const float*)d_in[7];
    const float* b3 = (const float*)d_in[8];
    const float* W4 = (const float*)d_in[9];
    const float* b4 = (const float*)d_in[10];
    float* out = (float*)d_out;

    int npts = in_sizes[0] / 3;
    int nblocks = (npts + PTILE - 1) / PTILE;

    cudaFuncSetAttribute(siren_mma_kernel,
                         cudaFuncAttributeMaxDynamicSharedMemorySize, SMEM_SZ);
    siren_mma_kernel<<<nblocks, NTHREADS, SMEM_SZ>>>(
        x, W0, b0, W1, b1, W2, b2, W3, b3, W4, b4, out, npts);
}

// round 11
// speedup vs baseline: 3.1802x; 1.2111x over previous
#include <cuda_runtime.h>
#include <cuda_bf16.h>
#include <cstdint>

// Fused SIREN MLP via warp-level bf16 HMMA: 3 -> 256 -> 256 -> 256 -> 256 -> 3
// Round 10: weights pre-converted to split-bf16 by a tiny prep kernel into a
// __device__ buffer (exact smem layout, chunk-contiguous); the main kernel
// stages chunks with pure cp.async (no conversion math, no fp32 weight LDG in
// the hot loop).  CTA = 128 points, 16 warps (4Mx4N), warp tile 32p x 64n.
// Split-bf16: D = Ahi*Whi + Alo*Whi + Ahi*Wlo (f32 acc).

#define NTHREADS 512
#define PTILE 128
#define HID 256
#define NCHUNK 8
#define AROWB 528          // A row stride (bytes): ldmatrix conflict-free
#define BROWB 80           // B row stride (bytes): conflict-free

#define A_HALF   67584     // 128 * 528
#define OFF_ALO  67584
#define OFF_B    135168
#define B_HALF   20480     // 256 * 80 (hi block; lo block follows)
#define B_BUF    40960     // hi + lo per chunk
#define OFF_PSUM 217088    // [4][128][3] f32
#define OFF_XS   223232
#define SMEM_SZ  224768

#define PREP_C   40960     // bytes per (chunk: hi+lo)
#define PREP_L   327680    // bytes per layer (8 chunks)

__device__ __align__(16) unsigned char g_prepW[3 * PREP_L];

__device__ __forceinline__ uint32_t smem_u32(const void* p) {
    uint32_t a;
    asm("{ .reg .u64 t; cvta.to.shared.u64 t, %1; cvt.u32.u64 %0, t; }"
        : "=r"(a) : "l"(p));
    return a;
}

__device__ __forceinline__ void ldsm4(uint32_t a[4], uint32_t addr) {
    asm volatile("ldmatrix.sync.aligned.m8n8.x4.shared.b16 {%0,%1,%2,%3}, [%4];"
                 : "=r"(a[0]), "=r"(a[1]), "=r"(a[2]), "=r"(a[3]) : "r"(addr));
}

__device__ __forceinline__ void mma16816(float d[4], const uint32_t a[4],
                                         uint32_t b0, uint32_t b1) {
    asm volatile("mma.sync.aligned.m16n8k16.row.col.f32.bf16.bf16.f32 "
                 "{%0,%1,%2,%3}, {%4,%5,%6,%7}, {%8,%9}, {%0,%1,%2,%3};"
                 : "+f"(d[0]), "+f"(d[1]), "+f"(d[2]), "+f"(d[3])
                 : "r"(a[0]), "r"(a[1]), "r"(a[2]), "r"(a[3]),
                   "r"(b0), "r"(b1));
}

__device__ __forceinline__ void cpa16(uint32_t dst, const void* src) {
    asm volatile("cp.async.cg.shared.global [%0], [%1], 16;"
                 :: "r"(dst), "l"(src) : "memory");
}
#define CP_COMMIT() asm volatile("cp.async.commit_group;" ::: "memory")
#define CP_WAIT0()  asm volatile("cp.async.wait_group 0;" ::: "memory")

__device__ __forceinline__ uint32_t packbf(float v0, float v1) {
    uint32_t r;
    asm("cvt.rn.bf16x2.f32 %0, %1, %2;" : "=r"(r) : "f"(v1), "f"(v0));
    return r;
}
__device__ __forceinline__ void split2(float s0, float s1,
                                       uint32_t& hi, uint32_t& lo) {
    hi = packbf(s0, s1);
    float h0 = __uint_as_float(hi << 16);
    float h1 = __uint_as_float(hi & 0xffff0000u);
    lo = packbf(s0 - h0, s1 - h1);
}

__device__ __forceinline__ float sin_small(float x) {   // |x| <= ~pi/2
    float x2 = x * x;
    float p = fmaf(2.7557314e-6f, x2, -1.9841271e-4f);
    p = fmaf(p, x2, 8.3333310e-3f);
    p = fmaf(p, x2, -1.6666667e-1f);
    return fmaf(p * x2, x, x);
}
__device__ __forceinline__ float sin_cw(float z) {      // |z| <= ~32
    float k = rintf(z * 0.318309886183790672f);
    float r = fmaf(k, -3.14159274101257324f, z);
    r = fmaf(k, 8.74227800296169792e-8f, r);
    float s = sin_small(r);
    return (((int)k) & 1) ? -s : s;
}

// ---- prep: W[L] fp32 [256][256] -> split-bf16 chunk-contiguous layout ----
__global__ void siren_prep_kernel(const float* __restrict__ W1,
                                  const float* __restrict__ W2,
                                  const float* __restrict__ W3) {
    int idx = blockIdx.x * blockDim.x + threadIdx.x;    // (L, n, kpair)
    if (idx >= 3 * 256 * 128) return;
    int L = idx / (256 * 128);
    int r = idx % (256 * 128);
    int n = r / 128;
    int k = (r % 128) * 2;
    const float* W = (L == 0) ? W1 : (L == 1) ? W2 : W3;
    float v0 = __ldg(W + n * HID + k);
    float v1 = __ldg(W + n * HID + k + 1);
    uint32_t hi, lo;
    split2(v0, v1, hi, lo);
    unsigned char* dst = g_prepW + L * PREP_L + (k >> 5) * PREP_C
                       + n * BROWB + (k & 31) * 2;
    *(uint32_t*)dst = hi;
    *(uint32_t*)(dst + B_HALF) = lo;
}

__global__ void __launch_bounds__(NTHREADS, 1) siren_mma_kernel(
    const float* __restrict__ x,
    const float* __restrict__ W0, const float* __restrict__ b0,
    const float* __restrict__ b1, const float* __restrict__ b2,
    const float* __restrict__ b3,
    const float* __restrict__ W4, const float* __restrict__ b4,
    float* __restrict__ out, int npts)
{
    extern __shared__ char smem[];
    const uint32_t sb = smem_u32(smem);
    const int tid = threadIdx.x;
    const int w = tid >> 5, l = tid & 31;
    const int mw = w & 3, nw = w >> 2;
    const int tile0 = blockIdx.x * PTILE;

    float* xs = (float*)(smem + OFF_XS);
    float* psum = (float*)(smem + OFF_PSUM);

    if (tid < PTILE * 3) {
        int idx = tile0 * 3 + tid;
        xs[tid] = (idx < npts * 3) ? x[idx] : 0.0f;
    }
    __syncthreads();

    // ---- layer 0: h0 = sin(30*(W0 x + b0)) -> A hi/lo (fp32-accurate) ----
    {
        int p = tid >> 2;
        int nb = (tid & 3) * 64;
        float x0 = xs[p * 3], x1 = xs[p * 3 + 1], x2 = xs[p * 3 + 2];
        char* ahr = smem + p * AROWB;
        char* alr = smem + OFF_ALO + p * AROWB;
#pragma unroll 8
        for (int j = 0; j < 64; j += 2) {
            int n = nb + j;
            float za = 30.0f * fmaf(__ldg(W0 + n * 3), x0,
                           fmaf(__ldg(W0 + n * 3 + 1), x1,
                           fmaf(__ldg(W0 + n * 3 + 2), x2, __ldg(b0 + n))));
            float zb = 30.0f * fmaf(__ldg(W0 + n * 3 + 3), x0,
                           fmaf(__ldg(W0 + n * 3 + 4), x1,
                           fmaf(__ldg(W0 + n * 3 + 5), x2, __ldg(b0 + n + 1))));
            uint32_t hi, lo;
            split2(sin_cw(za), sin_cw(zb), hi, lo);
            *(uint32_t*)(ahr + n * 2) = hi;
            *(uint32_t*)(alr + n * 2) = lo;
        }
    }
    __syncthreads();

    // ---- ldmatrix per-lane addresses ----
    const int lt = l >> 3, l7 = l & 7;
    const uint32_t aBase = sb + (uint32_t)((mw * 32 + l7 + ((lt & 1) << 3)) * AROWB
                                           + (((lt >> 1) << 3) * 2));
    const uint32_t bBase = sb + OFF_B
        + (uint32_t)((nw * 64 + l7 + ((lt >> 1) << 3)) * BROWB
                     + (((lt & 1) << 3) * 2));

    // cp.async staging addresses: thread copies 5 x 16B at stride 8192
    const uint32_t stDst = sb + OFF_B + (uint32_t)(tid * 16);

#pragma unroll 1
    for (int L = 0; L < 3; L++) {
        const float* bb = (L == 0) ? b1 : (L == 1) ? b2 : b3;
        const unsigned char* prepL = g_prepW + L * PREP_L;

        float acc[2][8][4];
#pragma unroll
        for (int mt = 0; mt < 2; mt++)
#pragma unroll
            for (int nt = 0; nt < 8; nt++)
#pragma unroll
                for (int q = 0; q < 4; q++) acc[mt][nt][q] = 0.0f;

        // issue chunk 0 -> buf 0
        {
            const unsigned char* src = prepL + tid * 16;
#pragma unroll
            for (int i = 0; i < 5; i++)
                cpa16(stDst + i * 8192, src + i * 8192);
            CP_COMMIT();
        }

#pragma unroll 1
        for (int c = 0; c < NCHUNK; c++) {
            CP_WAIT0();
            __syncthreads();   // chunk c staged; all chunk c-1 MMAs done

            if (c + 1 < NCHUNK) {
                const unsigned char* src = prepL + (c + 1) * PREP_C + tid * 16;
                uint32_t dst = stDst + (uint32_t)(((c + 1) & 1) * B_BUF);
#pragma unroll
                for (int i = 0; i < 5; i++)
                    cpa16(dst + i * 8192, src + i * 8192);
                CP_COMMIT();
            }

            const uint32_t bufB = bBase + (uint32_t)((c & 1) * B_BUF);
#pragma unroll
            for (int s = 0; s < 2; s++) {
                const int kk = c * 2 + s;
                uint32_t ahi[2][4], alo[2][4];
                ldsm4(ahi[0], aBase + kk * 32);
                ldsm4(ahi[1], aBase + 16 * AROWB + kk * 32);
                ldsm4(alo[0], aBase + A_HALF + kk * 32);
                ldsm4(alo[1], aBase + A_HALF + 16 * AROWB + kk * 32);
#pragma unroll
                for (int np = 0; np < 4; np++) {
                    uint32_t bh[4], bl[4];
                    uint32_t ba = bufB + np * 16 * BROWB + s * 32;
                    ldsm4(bh, ba);
                    ldsm4(bl, ba + B_HALF);
#pragma unroll
                    for (int mt = 0; mt < 2; mt++) {
                        mma16816(acc[mt][2 * np],     ahi[mt], bh[0], bh[1]);
                        mma16816(acc[mt][2 * np],     alo[mt], bh[0], bh[1]);
                        mma16816(acc[mt][2 * np],     ahi[mt], bl[0], bl[1]);
                        mma16816(acc[mt][2 * np + 1], ahi[mt], bh[2], bh[3]);
                        mma16816(acc[mt][2 * np + 1], alo[mt], bh[2], bh[3]);
                        mma16816(acc[mt][2 * np + 1], ahi[mt], bl[2], bl[3]);
                    }
                }
            }
        }
        __syncthreads();   // all MMAs done before A is overwritten

        if (L < 2) {
            // epilogue: sin(D + b) -> split bf16 -> A (in place)
#pragma unroll
            for (int mt = 0; mt < 2; mt++) {
                int pr = mw * 32 + mt * 16 + (l >> 2);
#pragma unroll
                for (int nt = 0; nt < 8; nt++) {
                    int nc = nw * 64 + nt * 8 + (l & 3) * 2;
                    float bn0 = __ldg(bb + nc), bn1 = __ldg(bb + nc + 1);
                    float s0 = sin_small(acc[mt][nt][0] + bn0);
                    float s1 = sin_small(acc[mt][nt][1] + bn1);
                    float s2 = sin_small(acc[mt][nt][2] + bn0);
                    float s3 = sin_small(acc[mt][nt][3] + bn1);
                    uint32_t h01, l01, h23, l23;
                    split2(s0, s1, h01, l01);
                    split2(s2, s3, h23, l23);
                    *(uint32_t*)(smem + pr * AROWB + nc * 2)                 = h01;
                    *(uint32_t*)(smem + OFF_ALO + pr * AROWB + nc * 2)       = l01;
                    *(uint32_t*)(smem + (pr + 8) * AROWB + nc * 2)           = h23;
                    *(uint32_t*)(smem + OFF_ALO + (pr + 8) * AROWB + nc * 2) = l23;
                }
            }
            __syncthreads();
        } else {
            // final: h3 = sin(D + b3); partial out_c = sum_n W4[c][n]*h3[n]
            float part[2][2][3];
#pragma unroll
            for (int mt = 0; mt < 2; mt++)
#pragma unroll
                for (int rh = 0; rh < 2; rh++)
#pragma unroll
                    for (int cc = 0; cc < 3; cc++) part[mt][rh][cc] = 0.0f;

#pragma unroll
            for (int mt = 0; mt < 2; mt++)
#pragma unroll
            for (int nt = 0; nt < 8; nt++) {
                int nc = nw * 64 + nt * 8 + (l & 3) * 2;
                float bn0 = __ldg(bb + nc), bn1 = __ldg(bb + nc + 1);
                float h0 = sin_small(acc[mt][nt][0] + bn0);
                float h1 = sin_small(acc[mt][nt][1] + bn1);
                float h2 = sin_small(acc[mt][nt][2] + bn0);
                float h3v = sin_small(acc[mt][nt][3] + bn1);
#pragma unroll
                for (int cc = 0; cc < 3; cc++) {
                    float w0v = __ldg(W4 + cc * HID + nc);
                    float w1v = __ldg(W4 + cc * HID + nc + 1);
                    part[mt][0][cc] = fmaf(w0v, h0, fmaf(w1v, h1, part[mt][0][cc]));
                    part[mt][1][cc] = fmaf(w0v, h2, fmaf(w1v, h3v, part[mt][1][cc]));
                }
            }
#pragma unroll
            for (int mt = 0; mt < 2; mt++)
#pragma unroll
            for (int rh = 0; rh < 2; rh++)
#pragma unroll
            for (int cc = 0; cc < 3; cc++) {
                float v = part[mt][rh][cc];
                v += __shfl_xor_sync(0xffffffffu, v, 1);
                v += __shfl_xor_sync(0xffffffffu, v, 2);
                part[mt][rh][cc] = v;
            }
            if ((l & 3) == 0) {
#pragma unroll
                for (int mt = 0; mt < 2; mt++)
#pragma unroll
                for (int rh = 0; rh < 2; rh++) {
                    int p = mw * 32 + mt * 16 + rh * 8 + (l >> 2);
#pragma unroll
                    for (int cc = 0; cc < 3; cc++)
                        psum[nw * 384 + p * 3 + cc] = part[mt][rh][cc];
                }
            }
        }
    }

    __syncthreads();
    if (tid < 384) {
        float v = psum[tid] + psum[384 + tid] + psum[768 + tid]
                + psum[1152 + tid] + __ldg(b4 + tid % 3);
        int idx = tile0 * 3 + tid;
        if (idx < npts * 3) out[idx] = v;
    }
}

extern "C" void kernel_launch(void* const* d_in, const int* in_sizes, int n_in,
                              void* d_out, int out_size) {
    const float* x  = (const float*)d_in[0];
    const float* W0 = (const float*)d_in[1];
    const float* b0 = (const float*)d_in[2];
    const float* W1 = (const float*)d_in[3];
    const float* b1 = (const float*)d_in[4];
    const float* W2 = (const float*)d_in[5];
    const float* b2 = (const float*)d_in[6];
    const float* W3 = (const float*)d_in[7];
    const float* b3 = (const float*)d_in[8];
    const float* W4 = (const float*)d_in[9];
    const float* b4 = (const float*)d_in[10];
    float* out = (float*)d_out;

    int npts = in_sizes[0] / 3;
    int nblocks = (npts + PTILE - 1) / PTILE;

    siren_prep_kernel<<<384, 256>>>(W1, W2, W3);

    cudaFuncSetAttribute(siren_mma_kernel,
                         cudaFuncAttributeMaxDynamicSharedMemorySize, SMEM_SZ);
    siren_mma_kernel<<<nblocks, NTHREADS, SMEM_SZ>>>(
        x, W0, b0, b1, b2, b3, W4, b4, out, npts);
}

// round 12
// speedup vs baseline: 3.2443x; 1.0202x over previous
#include <cuda_runtime.h>
#include <cuda_bf16.h>
#include <cstdint>

// Fused SIREN MLP via warp-level bf16 HMMA: 3 -> 256 -> 256 -> 256 -> 256 -> 3
// Round 11: (1) product-major MMA emission (same-acc RAW distance 1 -> 4),
// (2) unified chunk index across layers so next-layer staging cp.async is
// issued before the epilogue and flies during it, (3) W1 chunk0 prefetched
// before layer-0 compute.  Otherwise identical to R10 (prep kernel converts
// weights to split-bf16 in the exact smem layout; hot loop stages via
// cp.async only).

#define NTHREADS 512
#define PTILE 128
#define HID 256
#define NCHUNK 8
#define AROWB 528
#define BROWB 80

#define A_HALF   67584
#define OFF_ALO  67584
#define OFF_B    135168
#define B_HALF   20480
#define B_BUF    40960
#define OFF_PSUM 217088
#define OFF_XS   223232
#define SMEM_SZ  224768

#define PREP_C   40960
#define PREP_L   327680
#define NT_TOTAL 24        // 3 layers x 8 chunks

__device__ __align__(16) unsigned char g_prepW[3 * PREP_L];

__device__ __forceinline__ uint32_t smem_u32(const void* p) {
    uint32_t a;
    asm("{ .reg .u64 t; cvta.to.shared.u64 t, %1; cvt.u32.u64 %0, t; }"
        : "=r"(a) : "l"(p));
    return a;
}

__device__ __forceinline__ void ldsm4(uint32_t a[4], uint32_t addr) {
    asm volatile("ldmatrix.sync.aligned.m8n8.x4.shared.b16 {%0,%1,%2,%3}, [%4];"
                 : "=r"(a[0]), "=r"(a[1]), "=r"(a[2]), "=r"(a[3]) : "r"(addr));
}

__device__ __forceinline__ void mma16816(float d[4], const uint32_t a[4],
                                         uint32_t b0, uint32_t b1) {
    asm volatile("mma.sync.aligned.m16n8k16.row.col.f32.bf16.bf16.f32 "
                 "{%0,%1,%2,%3}, {%4,%5,%6,%7}, {%8,%9}, {%0,%1,%2,%3};"
                 : "+f"(d[0]), "+f"(d[1]), "+f"(d[2]), "+f"(d[3])
                 : "r"(a[0]), "r"(a[1]), "r"(a[2]), "r"(a[3]),
                   "r"(b0), "r"(b1));
}

__device__ __forceinline__ void cpa16(uint32_t dst, const void* src) {
    asm volatile("cp.async.cg.shared.global [%0], [%1], 16;"
                 :: "r"(dst), "l"(src) : "memory");
}
#define CP_COMMIT() asm volatile("cp.async.commit_group;" ::: "memory")
#define CP_WAIT0()  asm volatile("cp.async.wait_group 0;" ::: "memory")

__device__ __forceinline__ uint32_t packbf(float v0, float v1) {
    uint32_t r;
    asm("cvt.rn.bf16x2.f32 %0, %1, %2;" : "=r"(r) : "f"(v1), "f"(v0));
    return r;
}
__device__ __forceinline__ void split2(float s0, float s1,
                                       uint32_t& hi, uint32_t& lo) {
    hi = packbf(s0, s1);
    float h0 = __uint_as_float(hi << 16);
    float h1 = __uint_as_float(hi & 0xffff0000u);
    lo = packbf(s0 - h0, s1 - h1);
}

__device__ __forceinline__ float sin_small(float x) {
    float x2 = x * x;
    float p = fmaf(2.7557314e-6f, x2, -1.9841271e-4f);
    p = fmaf(p, x2, 8.3333310e-3f);
    p = fmaf(p, x2, -1.6666667e-1f);
    return fmaf(p * x2, x, x);
}
__device__ __forceinline__ float sin_cw(float z) {
    float k = rintf(z * 0.318309886183790672f);
    float r = fmaf(k, -3.14159274101257324f, z);
    r = fmaf(k, 8.74227800296169792e-8f, r);
    float s = sin_small(r);
    return (((int)k) & 1) ? -s : s;
}

// ---- prep: W[L] fp32 [256][256] -> split-bf16 chunk-contiguous layout ----
__global__ void siren_prep_kernel(const float* __restrict__ W1,
                                  const float* __restrict__ W2,
                                  const float* __restrict__ W3) {
    int idx = blockIdx.x * blockDim.x + threadIdx.x;
    if (idx >= 3 * 256 * 128) return;
    int L = idx / (256 * 128);
    int r = idx % (256 * 128);
    int n = r / 128;
    int k = (r % 128) * 2;
    const float* W = (L == 0) ? W1 : (L == 1) ? W2 : W3;
    float v0 = __ldg(W + n * HID + k);
    float v1 = __ldg(W + n * HID + k + 1);
    uint32_t hi, lo;
    split2(v0, v1, hi, lo);
    unsigned char* dst = g_prepW + L * PREP_L + (k >> 5) * PREP_C
                       + n * BROWB + (k & 31) * 2;
    *(uint32_t*)dst = hi;
    *(uint32_t*)(dst + B_HALF) = lo;
}

__global__ void __launch_bounds__(NTHREADS, 1) siren_mma_kernel(
    const float* __restrict__ x,
    const float* __restrict__ W0, const float* __restrict__ b0,
    const float* __restrict__ b1, const float* __restrict__ b2,
    const float* __restrict__ b3,
    const float* __restrict__ W4, const float* __restrict__ b4,
    float* __restrict__ out, int npts)
{
    extern __shared__ char smem[];
    const uint32_t sb = smem_u32(smem);
    const int tid = threadIdx.x;
    const int w = tid >> 5, l = tid & 31;
    const int mw = w & 3, nw = w >> 2;
    const int tile0 = blockIdx.x * PTILE;

    float* xs = (float*)(smem + OFF_XS);
    float* psum = (float*)(smem + OFF_PSUM);

    const uint32_t stDst = sb + OFF_B + (uint32_t)(tid * 16);

    if (tid < PTILE * 3) {
        int idx = tile0 * 3 + tid;
        xs[tid] = (idx < npts * 3) ? x[idx] : 0.0f;
    }

    // prefetch layer-1 weights chunk 0 (t = 0) while layer 0 computes
    {
        const unsigned char* src = g_prepW + tid * 16;
#pragma unroll
        for (int i = 0; i < 5; i++)
            cpa16(stDst + i * 8192, src + i * 8192);
        CP_COMMIT();
    }
    __syncthreads();

    // ---- layer 0: h0 = sin(30*(W0 x + b0)) -> A hi/lo (fp32-accurate) ----
    {
        int p = tid >> 2;
        int nb = (tid & 3) * 64;
        float x0 = xs[p * 3], x1 = xs[p * 3 + 1], x2 = xs[p * 3 + 2];
        char* ahr = smem + p * AROWB;
        char* alr = smem + OFF_ALO + p * AROWB;
#pragma unroll 8
        for (int j = 0; j < 64; j += 2) {
            int n = nb + j;
            float za = 30.0f * fmaf(__ldg(W0 + n * 3), x0,
                           fmaf(__ldg(W0 + n * 3 + 1), x1,
                           fmaf(__ldg(W0 + n * 3 + 2), x2, __ldg(b0 + n))));
            float zb = 30.0f * fmaf(__ldg(W0 + n * 3 + 3), x0,
                           fmaf(__ldg(W0 + n * 3 + 4), x1,
                           fmaf(__ldg(W0 + n * 3 + 5), x2, __ldg(b0 + n + 1))));
            uint32_t hi, lo;
            split2(sin_cw(za), sin_cw(zb), hi, lo);
            *(uint32_t*)(ahr + n * 2) = hi;
            *(uint32_t*)(alr + n * 2) = lo;
        }
    }

    // ---- ldmatrix per-lane addresses ----
    const int lt = l >> 3, l7 = l & 7;
    const uint32_t aBase = sb + (uint32_t)((mw * 32 + l7 + ((lt & 1) << 3)) * AROWB
                                           + (((lt >> 1) << 3) * 2));
    const uint32_t bBase = sb + OFF_B
        + (uint32_t)((nw * 64 + l7 + ((lt >> 1) << 3)) * BROWB
                     + (((lt & 1) << 3) * 2));

#pragma unroll 1
    for (int L = 0; L < 3; L++) {
        const float* bb = (L == 0) ? b1 : (L == 1) ? b2 : b3;

        float acc[2][8][4];
#pragma unroll
        for (int mt = 0; mt < 2; mt++)
#pragma unroll
            for (int nt = 0; nt < 8; nt++)
#pragma unroll
                for (int q = 0; q < 4; q++) acc[mt][nt][q] = 0.0f;

#pragma unroll 1
        for (int c = 0; c < NCHUNK; c++) {
            const int t = L * NCHUNK + c;
            CP_WAIT0();
            __syncthreads();   // chunk t staged; chunk t-1 MMAs done (all warps)

            if (t + 1 < NT_TOTAL) {
                // may be next layer's chunk 0 -> overlaps with epilogue
                const unsigned char* src = g_prepW + (t + 1) * PREP_C + tid * 16;
                uint32_t dst = stDst + (uint32_t)(((t + 1) & 1) * B_BUF);
#pragma unroll
                for (int i = 0; i < 5; i++)
                    cpa16(dst + i * 8192, src + i * 8192);
                CP_COMMIT();
            }

            const uint32_t bufB = bBase + (uint32_t)((t & 1) * B_BUF);
#pragma unroll
            for (int s = 0; s < 2; s++) {
                const int kk = c * 2 + s;
                uint32_t ahi[2][4], alo[2][4];
                ldsm4(ahi[0], aBase + kk * 32);
                ldsm4(ahi[1], aBase + 16 * AROWB + kk * 32);
                ldsm4(alo[0], aBase + A_HALF + kk * 32);
                ldsm4(alo[1], aBase + A_HALF + 16 * AROWB + kk * 32);
#pragma unroll
                for (int np = 0; np < 4; np++) {
                    uint32_t bh[4], bl[4];
                    uint32_t ba = bufB + np * 16 * BROWB + s * 32;
                    ldsm4(bh, ba);
                    ldsm4(bl, ba + B_HALF);
                    // product-major: same-acc RAW distance = 4
                    mma16816(acc[0][2 * np],     ahi[0], bh[0], bh[1]);
                    mma16816(acc[1][2 * np],     ahi[1], bh[0], bh[1]);
                    mma16816(acc[0][2 * np + 1], ahi[0], bh[2], bh[3]);
                    mma16816(acc[1][2 * np + 1], ahi[1], bh[2], bh[3]);
                    mma16816(acc[0][2 * np],     alo[0], bh[0], bh[1]);
                    mma16816(acc[1][2 * np],     alo[1], bh[0], bh[1]);
                    mma16816(acc[0][2 * np + 1], alo[0], bh[2], bh[3]);
                    mma16816(acc[1][2 * np + 1], alo[1], bh[2], bh[3]);
                    mma16816(acc[0][2 * np],     ahi[0], bl[0], bl[1]);
                    mma16816(acc[1][2 * np],     ahi[1], bl[0], bl[1]);
                    mma16816(acc[0][2 * np + 1], ahi[0], bl[2], bl[3]);
                    mma16816(acc[1][2 * np + 1], ahi[1], bl[2], bl[3]);
                }
            }
        }
        __syncthreads();   // all MMAs done before A is overwritten

        if (L < 2) {
            // epilogue: sin(D + b) -> split bf16 -> A in place
            // (next layer's chunk 0 cp.async is in flight during this)
#pragma unroll
            for (int mt = 0; mt < 2; mt++) {
                int pr = mw * 32 + mt * 16 + (l >> 2);
#pragma unroll
                for (int nt = 0; nt < 8; nt++) {
                    int nc = nw * 64 + nt * 8 + (l & 3) * 2;
                    float bn0 = __ldg(bb + nc), bn1 = __ldg(bb + nc + 1);
                    float s0 = sin_small(acc[mt][nt][0] + bn0);
                    float s1 = sin_small(acc[mt][nt][1] + bn1);
                    float s2 = sin_small(acc[mt][nt][2] + bn0);
                    float s3 = sin_small(acc[mt][nt][3] + bn1);
                    uint32_t h01, l01, h23, l23;
                    split2(s0, s1, h01, l01);
                    split2(s2, s3, h23, l23);
                    *(uint32_t*)(smem + pr * AROWB + nc * 2)                 = h01;
                    *(uint32_t*)(smem + OFF_ALO + pr * AROWB + nc * 2)       = l01;
                    *(uint32_t*)(smem + (pr + 8) * AROWB + nc * 2)           = h23;
                    *(uint32_t*)(smem + OFF_ALO + (pr + 8) * AROWB + nc * 2) = l23;
                }
            }
            __syncthreads();
        } else {
            // final: h3 = sin(D + b3); partial out_c = sum_n W4[c][n]*h3[n]
            float part[2][2][3];
#pragma unroll
            for (int mt = 0; mt < 2; mt++)
#pragma unroll
                for (int rh = 0; rh < 2; rh++)
#pragma unroll
                    for (int cc = 0; cc < 3; cc++) part[mt][rh][cc] = 0.0f;

#pragma unroll
            for (int mt = 0; mt < 2; mt++)
#pragma unroll
            for (int nt = 0; nt < 8; nt++) {
                int nc = nw * 64 + nt * 8 + (l & 3) * 2;
                float bn0 = __ldg(bb + nc), bn1 = __ldg(bb + nc + 1);
                float h0 = sin_small(acc[mt][nt][0] + bn0);
                float h1 = sin_small(acc[mt][nt][1] + bn1);
                float h2 = sin_small(acc[mt][nt][2] + bn0);
                float h3v = sin_small(acc[mt][nt][3] + bn1);
#pragma unroll
                for (int cc = 0; cc < 3; cc++) {
                    float w0v = __ldg(W4 + cc * HID + nc);
                    float w1v = __ldg(W4 + cc * HID + nc + 1);
                    part[mt][0][cc] = fmaf(w0v, h0, fmaf(w1v, h1, part[mt][0][cc]));
                    part[mt][1][cc] = fmaf(w0v, h2, fmaf(w1v, h3v, part[mt][1][cc]));
                }
            }
#pragma unroll
            for (int mt = 0; mt < 2; mt++)
#pragma unroll
            for (int rh = 0; rh < 2; rh++)
#pragma unroll
            for (int cc = 0; cc < 3; cc++) {
                float v = part[mt][rh][cc];
                v += __shfl_xor_sync(0xffffffffu, v, 1);
                v += __shfl_xor_sync(0xffffffffu, v, 2);
                part[mt][rh][cc] = v;
            }
            if ((l & 3) == 0) {
#pragma unroll
                for (int mt = 0; mt < 2; mt++)
#pragma unroll
                for (int rh = 0; rh < 2; rh++) {
                    int p = mw * 32 + mt * 16 + rh * 8 + (l >> 2);
#pragma unroll
                    for (int cc = 0; cc < 3; cc++)
                        psum[nw * 384 + p * 3 + cc] = part[mt][rh][cc];
                }
            }
        }
    }

    __syncthreads();
    if (tid < 384) {
        float v = psum[tid] + psum[384 + tid] + psum[768 + tid]
                + psum[1152 + tid] + __ldg(b4 + tid % 3);
        int idx = tile0 * 3 + tid;
        if (idx < npts * 3) out[idx] = v;
    }
}

extern "C" void kernel_launch(void* const* d_in, const int* in_sizes, int n_in,
                              void* d_out, int out_size) {
    const float* x  = (const float*)d_in[0];
    const float* W0 = (const float*)d_in[1];
    const float* b0 = (const float*)d_in[2];
    const float* W1 = (const float*)d_in[3];
    const float* b1 = (const float*)d_in[4];
    const float* W2 = (const float*)d_in[5];
    const float* b2 = (const float*)d_in[6];
    const float* W3 = (const float*)d_in[7];
    const float* b3 = (const float*)d_in[8];
    const float* W4 = (const float*)d_in[9];
    const float* b4 = (const float*)d_in[10];
    float* out = (float*)d_out;

    int npts = in_sizes[0] / 3;
    int nblocks = (npts + PTILE - 1) / PTILE;

    siren_prep_kernel<<<384, 256>>>(W1, W2, W3);

    cudaFuncSetAttribute(siren_mma_kernel,
                         cudaFuncAttributeMaxDynamicSharedMemorySize, SMEM_SZ);
    siren_mma_kernel<<<nblocks, NTHREADS, SMEM_SZ>>>(
        x, W0, b0, b1, b2, b3, W4, b4, out, npts);
}

// round 13
// speedup vs baseline: 6.5115x; 2.0070x over previous
#include <cuda_runtime.h>
#include <cuda_bf16.h>
#include <cstdint>

// Fused SIREN MLP via single-product fp16 HMMA: 3 -> 256 -> 256 -> 256 -> 256 -> 3
// Round 12: (1) ONE fp16 MMA per k16 (was 3 split-bf16) with static power-of-2
// activation scaling (a = h*S, S = {1,16,512}) to keep fp16 operands in normal
// range; (2) PTILE=64 / 256 threads / 78.6KB smem -> 2 CTAs per SM so
// barriers, epilogues and layer-0 of one CTA overlap the other CTA's MMAs.
// CTA = 8 warps (2M x 4N), warp tile 32p x 64n.  Prep kernel converts weights
// fp32 -> fp16 in the exact smem layout; hot loop stages via cp.async only.

#define NTHREADS 256
#define PTILE 64
#define HID 256
#define NCHUNK 8
#define AROWB 528          // A row stride (bytes): 256 fp16 + pad, ldsm conflict-free
#define BROWB 80           // B row stride (bytes): 32 fp16 + pad, conflict-free

#define OFF_B    33792     // A = [64][AROWB] fp16 ends here
#define B_BUF    20480     // one chunk: 256n x 32k fp16 (80B rows)
#define OFF_PSUM 74752     // [4][64][3] f32 = 3072
#define OFF_XS   77824     // 64*3 f32 = 768
#define SMEM_SZ  78592

#define PREP_C   20480
#define PREP_L   163840
#define NT_TOTAL 24        // 3 layers x 8 chunks

__device__ __align__(16) unsigned char g_prepW[3 * PREP_L];

__device__ __forceinline__ uint32_t smem_u32(const void* p) {
    uint32_t a;
    asm("{ .reg .u64 t; cvta.to.shared.u64 t, %1; cvt.u32.u64 %0, t; }"
        : "=r"(a) : "l"(p));
    return a;
}

__device__ __forceinline__ void ldsm4(uint32_t a[4], uint32_t addr) {
    asm volatile("ldmatrix.sync.aligned.m8n8.x4.shared.b16 {%0,%1,%2,%3}, [%4];"
                 : "=r"(a[0]), "=r"(a[1]), "=r"(a[2]), "=r"(a[3]) : "r"(addr));
}

__device__ __forceinline__ void mma16816(float d[4], const uint32_t a[4],
                                         uint32_t b0, uint32_t b1) {
    asm volatile("mma.sync.aligned.m16n8k16.row.col.f32.f16.f16.f32 "
                 "{%0,%1,%2,%3}, {%4,%5,%6,%7}, {%8,%9}, {%0,%1,%2,%3};"
                 : "+f"(d[0]), "+f"(d[1]), "+f"(d[2]), "+f"(d[3])
                 : "r"(a[0]), "r"(a[1]), "r"(a[2]), "r"(a[3]),
                   "r"(b0), "r"(b1));
}

__device__ __forceinline__ void cpa16(uint32_t dst, const void* src) {
    asm volatile("cp.async.cg.shared.global [%0], [%1], 16;"
                 :: "r"(dst), "l"(src) : "memory");
}
#define CP_COMMIT() asm volatile("cp.async.commit_group;" ::: "memory")
#define CP_WAIT0()  asm volatile("cp.async.wait_group 0;" ::: "memory")

// pack two fp32 -> fp16x2 (v0 in low half)
__device__ __forceinline__ uint32_t packh(float v0, float v1) {
    uint32_t r;
    asm("cvt.rn.f16x2.f32 %0, %1, %2;" : "=r"(r) : "f"(v1), "f"(v0));
    return r;
}

__device__ __forceinline__ float sin_small(float x) {   // |x| <= ~pi/2
    float x2 = x * x;
    float p = fmaf(2.7557314e-6f, x2, -1.9841271e-4f);
    p = fmaf(p, x2, 8.3333310e-3f);
    p = fmaf(p, x2, -1.6666667e-1f);
    return fmaf(p * x2, x, x);
}
__device__ __forceinline__ float sin_cw(float z) {      // |z| <= ~32
    float k = rintf(z * 0.318309886183790672f);
    float r = fmaf(k, -3.14159274101257324f, z);
    r = fmaf(k, 8.74227800296169792e-8f, r);
    float s = sin_small(r);
    return (((int)k) & 1) ? -s : s;
}

// ---- prep: W[L] fp32 [256][256] -> fp16 chunk-contiguous layout ----
__global__ void siren_prep_kernel(const float* __restrict__ W1,
                                  const float* __restrict__ W2,
                                  const float* __restrict__ W3) {
    int idx = blockIdx.x * blockDim.x + threadIdx.x;
    if (idx >= 3 * 256 * 128) return;
    int L = idx / (256 * 128);
    int r = idx % (256 * 128);
    int n = r / 128;
    int k = (r % 128) * 2;
    const float* W = (L == 0) ? W1 : (L == 1) ? W2 : W3;
    float v0 = __ldg(W + n * HID + k);
    float v1 = __ldg(W + n * HID + k + 1);
    unsigned char* dst = g_prepW + L * PREP_L + (k >> 5) * PREP_C
                       + n * BROWB + (k & 31) * 2;
    *(uint32_t*)dst = packh(v0, v1);
}

__global__ void __launch_bounds__(NTHREADS, 2) siren_mma_kernel(
    const float* __restrict__ x,
    const float* __restrict__ W0, const float* __restrict__ b0,
    const float* __restrict__ b1, const float* __restrict__ b2,
    const float* __restrict__ b3,
    const float* __restrict__ W4, const float* __restrict__ b4,
    float* __restrict__ out, int npts)
{
    extern __shared__ char smem[];
    const uint32_t sb = smem_u32(smem);
    const int tid = threadIdx.x;
    const int w = tid >> 5, l = tid & 31;
    const int mw = w & 1, nw = w >> 1;       // 2 M-groups x 4 N-groups
    const int tile0 = blockIdx.x * PTILE;

    float* xs = (float*)(smem + OFF_XS);
    float* psum = (float*)(smem + OFF_PSUM);

    const uint32_t stDst = sb + OFF_B + (uint32_t)(tid * 16);

    if (tid < PTILE * 3) {
        int idx = tile0 * 3 + tid;
        xs[tid] = (idx < npts * 3) ? x[idx] : 0.0f;
    }

    // prefetch layer-1 weights chunk 0 while layer 0 computes
    {
        const unsigned char* src = g_prepW + tid * 16;
#pragma unroll
        for (int i = 0; i < 5; i++)
            cpa16(stDst + i * 4096, src + i * 4096);
        CP_COMMIT();
    }
    __syncthreads();

    // ---- layer 0: a0 = sin(30*(W0 x + b0))  (S0 = 1), fp16 -> A ----
    {
        int p = tid >> 2;                    // 0..63
        int nb = (tid & 3) * 64;
        float x0 = xs[p * 3], x1 = xs[p * 3 + 1], x2 = xs[p * 3 + 2];
        char* ar = smem + p * AROWB;
#pragma unroll 8
        for (int j = 0; j < 64; j += 2) {
            int n = nb + j;
            float za = 30.0f * fmaf(__ldg(W0 + n * 3), x0,
                           fmaf(__ldg(W0 + n * 3 + 1), x1,
                           fmaf(__ldg(W0 + n * 3 + 2), x2, __ldg(b0 + n))));
            float zb = 30.0f * fmaf(__ldg(W0 + n * 3 + 3), x0,
                           fmaf(__ldg(W0 + n * 3 + 4), x1,
                           fmaf(__ldg(W0 + n * 3 + 5), x2, __ldg(b0 + n + 1))));
            *(uint32_t*)(ar + n * 2) = packh(sin_cw(za), sin_cw(zb));
        }
    }

    // ---- ldmatrix per-lane addresses ----
    const int lt = l >> 3, l7 = l & 7;
    const uint32_t aBase = sb + (uint32_t)((mw * 32 + l7 + ((lt & 1) << 3)) * AROWB
                                           + (((lt >> 1) << 3) * 2));
    const uint32_t bBase = sb + OFF_B
        + (uint32_t)((nw * 64 + l7 + ((lt >> 1) << 3)) * BROWB
                     + (((lt & 1) << 3) * 2));

    // activation scaling: a_L = h_L * S[L];  epilogue: z = y*invS + b
    const float invS[3] = {1.0f, 1.0f / 16.0f, 1.0f / 512.0f};
    const float Sout[2] = {16.0f, 512.0f};

#pragma unroll 1
    for (int L = 0; L < 3; L++) {
        const float* bb = (L == 0) ? b1 : (L == 1) ? b2 : b3;
        const float is = invS[L];

        float acc[2][8][4];
#pragma unroll
        for (int mt = 0; mt < 2; mt++)
#pragma unroll
            for (int nt = 0; nt < 8; nt++)
#pragma unroll
                for (int q = 0; q < 4; q++) acc[mt][nt][q] = 0.0f;

#pragma unroll 1
        for (int c = 0; c < NCHUNK; c++) {
            const int t = L * NCHUNK + c;
            CP_WAIT0();
            __syncthreads();   // chunk t staged; chunk t-1 MMAs done

            if (t + 1 < NT_TOTAL) {
                const unsigned char* src = g_prepW + (t + 1) * PREP_C + tid * 16;
                uint32_t dst = stDst + (uint32_t)(((t + 1) & 1) * B_BUF);
#pragma unroll
                for (int i = 0; i < 5; i++)
                    cpa16(dst + i * 4096, src + i * 4096);
                CP_COMMIT();
            }

            const uint32_t bufB = bBase + (uint32_t)((t & 1) * B_BUF);
#pragma unroll
            for (int s = 0; s < 2; s++) {
                const int kk = c * 2 + s;
                uint32_t af[2][4];
                ldsm4(af[0], aBase + kk * 32);
                ldsm4(af[1], aBase + 16 * AROWB + kk * 32);
#pragma unroll
                for (int np = 0; np < 4; np++) {
                    uint32_t bf[4];
                    ldsm4(bf, bufB + np * 16 * BROWB + s * 32);
                    mma16816(acc[0][2 * np],     af[0], bf[0], bf[1]);
                    mma16816(acc[1][2 * np],     af[1], bf[0], bf[1]);
                    mma16816(acc[0][2 * np + 1], af[0], bf[2], bf[3]);
                    mma16816(acc[1][2 * np + 1], af[1], bf[2], bf[3]);
                }
            }
        }
        __syncthreads();   // all MMAs done before A is overwritten

        if (L < 2) {
            // epilogue: a_next = sin(y*invS + b) * Sout  -> A in place (fp16)
            const float so = Sout[L];
#pragma unroll
            for (int mt = 0; mt < 2; mt++) {
                int pr = mw * 32 + mt * 16 + (l >> 2);
#pragma unroll
                for (int nt = 0; nt < 8; nt++) {
                    int nc = nw * 64 + nt * 8 + (l & 3) * 2;
                    float bn0 = __ldg(bb + nc), bn1 = __ldg(bb + nc + 1);
                    float s0 = sin_small(fmaf(acc[mt][nt][0], is, bn0)) * so;
                    float s1 = sin_small(fmaf(acc[mt][nt][1], is, bn1)) * so;
                    float s2 = sin_small(fmaf(acc[mt][nt][2], is, bn0)) * so;
                    float s3 = sin_small(fmaf(acc[mt][nt][3], is, bn1)) * so;
                    *(uint32_t*)(smem + pr * AROWB + nc * 2)       = packh(s0, s1);
                    *(uint32_t*)(smem + (pr + 8) * AROWB + nc * 2) = packh(s2, s3);
                }
            }
            __syncthreads();
        } else {
            // final: h3 = sin(y*invS + b3); partial out_c = sum_n W4[c][n]*h3[n]
            float part[2][2][3];
#pragma unroll
            for (int mt = 0; mt < 2; mt++)
#pragma unroll
                for (int rh = 0; rh < 2; rh++)
#pragma unroll
                    for (int cc = 0; cc < 3; cc++) part[mt][rh][cc] = 0.0f;

#pragma unroll
            for (int mt = 0; mt < 2; mt++)
#pragma unroll
            for (int nt = 0; nt < 8; nt++) {
                int nc = nw * 64 + nt * 8 + (l & 3) * 2;
                float bn0 = __ldg(bb + nc), bn1 = __ldg(bb + nc + 1);
                float h0 = sin_small(fmaf(acc[mt][nt][0], is, bn0));
                float h1 = sin_small(fmaf(acc[mt][nt][1], is, bn1));
                float h2 = sin_small(fmaf(acc[mt][nt][2], is, bn0));
                float h3v = sin_small(fmaf(acc[mt][nt][3], is, bn1));
#pragma unroll
                for (int cc = 0; cc < 3; cc++) {
                    float w0v = __ldg(W4 + cc * HID + nc);
                    float w1v = __ldg(W4 + cc * HID + nc + 1);
                    part[mt][0][cc] = fmaf(w0v, h0, fmaf(w1v, h1, part[mt][0][cc]));
                    part[mt][1][cc] = fmaf(w0v, h2, fmaf(w1v, h3v, part[mt][1][cc]));
                }
            }
#pragma unroll
            for (int mt = 0; mt < 2; mt++)
#pragma unroll
            for (int rh = 0; rh < 2; rh++)
#pragma unroll
            for (int cc = 0; cc < 3; cc++) {
                float v = part[mt][rh][cc];
                v += __shfl_xor_sync(0xffffffffu, v, 1);
                v += __shfl_xor_sync(0xffffffffu, v, 2);
                part[mt][rh][cc] = v;
            }
            if ((l & 3) == 0) {
#pragma unroll
                for (int mt = 0; mt < 2; mt++)
#pragma unroll
                for (int rh = 0; rh < 2; rh++) {
                    int p = mw * 32 + mt * 16 + rh * 8 + (l >> 2);
#pragma unroll
                    for (int cc = 0; cc < 3; cc++)
                        psum[nw * 192 + p * 3 + cc] = part[mt][rh][cc];
                }
            }
        }
    }

    __syncthreads();
    if (tid < PTILE * 3) {
        float v = psum[tid] + psum[192 + tid] + psum[384 + tid]
                + psum[576 + tid] + __ldg(b4 + tid % 3);
        int idx = tile0 * 3 + tid;
        if (idx < npts * 3) out[idx] = v;
    }
}

extern "C" void kernel_launch(void* const* d_in, const int* in_sizes, int n_in,
                              void* d_out, int out_size) {
    const float* x  = (const float*)d_in[0];
    const float* W0 = (const float*)d_in[1];
    const float* b0 = (const float*)d_in[2];
    const float* W1 = (const float*)d_in[3];
    const float* b1 = (const float*)d_in[4];
    const float* W2 = (const float*)d_in[5];
    const float* b2 = (const float*)d_in[6];
    const float* W3 = (const float*)d_in[7];
    const float* b3 = (const float*)d_in[8];
    const float* W4 = (const float*)d_in[9];
    const float* b4 = (const float*)d_in[10];
    float* out = (float*)d_out;

    int npts = in_sizes[0] / 3;
    int nblocks = (npts + PTILE - 1) / PTILE;

    siren_prep_kernel<<<384, 256>>>(W1, W2, W3);

    cudaFuncSetAttribute(siren_mma_kernel,
                         cudaFuncAttributeMaxDynamicSharedMemorySize, SMEM_SZ);
    siren_mma_kernel<<<nblocks, NTHREADS, SMEM_SZ>>>(
        x, W0, b0, b1, b2, b3, W4, b4, out, npts);
}

// round 14
// speedup vs baseline: 7.9151x; 1.2156x over previous
#include <cuda_runtime.h>
#include <cuda_bf16.h>
#include <cstdint>

// Fused SIREN MLP via single-product fp16 HMMA: 3 -> 256 -> 256 -> 256 -> 256 -> 3
// Round 13: all activation math in packed f32x2 (2 sins per instruction
// stream), packed Cody-Waite for layer 0 (magic-number rint + per-lane sign),
// warp-uniform layer-0 weight loads, float2 bias/W4 loads.
// Same MMA skeleton as R12: PTILE=64, 256 thr, 2 CTAs/SM, prep kernel converts
// weights fp32->fp16 in smem layout, cp.async staging, static activation
// scaling S = {1,16,512} to keep fp16 operands normal.

#define NTHREADS 256
#define PTILE 64
#define HID 256
#define NCHUNK 8
#define AROWB 528
#define BROWB 80

#define OFF_B    33792
#define B_BUF    20480
#define OFF_PSUM 74752
#define OFF_XS   77824
#define SMEM_SZ  78592

#define PREP_C   20480
#define PREP_L   163840
#define NT_TOTAL 24

typedef unsigned long long ull;

__device__ __align__(16) unsigned char g_prepW[3 * PREP_L];

__device__ __forceinline__ uint32_t smem_u32(const void* p) {
    uint32_t a;
    asm("{ .reg .u64 t; cvta.to.shared.u64 t, %1; cvt.u32.u64 %0, t; }"
        : "=r"(a) : "l"(p));
    return a;
}

__device__ __forceinline__ void ldsm4(uint32_t a[4], uint32_t addr) {
    asm volatile("ldmatrix.sync.aligned.m8n8.x4.shared.b16 {%0,%1,%2,%3}, [%4];"
                 : "=r"(a[0]), "=r"(a[1]), "=r"(a[2]), "=r"(a[3]) : "r"(addr));
}

__device__ __forceinline__ void mma16816(float d[4], const uint32_t a[4],
                                         uint32_t b0, uint32_t b1) {
    asm volatile("mma.sync.aligned.m16n8k16.row.col.f32.f16.f16.f32 "
                 "{%0,%1,%2,%3}, {%4,%5,%6,%7}, {%8,%9}, {%0,%1,%2,%3};"
                 : "+f"(d[0]), "+f"(d[1]), "+f"(d[2]), "+f"(d[3])
                 : "r"(a[0]), "r"(a[1]), "r"(a[2]), "r"(a[3]),
                   "r"(b0), "r"(b1));
}

__device__ __forceinline__ void cpa16(uint32_t dst, const void* src) {
    asm volatile("cp.async.cg.shared.global [%0], [%1], 16;"
                 :: "r"(dst), "l"(src) : "memory");
}
#define CP_COMMIT() asm volatile("cp.async.commit_group;" ::: "memory")
#define CP_WAIT0()  asm volatile("cp.async.wait_group 0;" ::: "memory")

// ---------------- packed f32x2 helpers ----------------
__device__ __forceinline__ ull fma2(ull a, ull b, ull c) {
    ull d;
    asm("fma.rn.f32x2 %0, %1, %2, %3;" : "=l"(d) : "l"(a), "l"(b), "l"(c));
    return d;
}
__device__ __forceinline__ ull mul2(ull a, ull b) {
    ull d;
    asm("mul.rn.f32x2 %0, %1, %2;" : "=l"(d) : "l"(a), "l"(b));
    return d;
}
__device__ __forceinline__ ull add2(ull a, ull b) {
    ull d;
    asm("add.rn.f32x2 %0, %1, %2;" : "=l"(d) : "l"(a), "l"(b));
    return d;
}
__device__ __forceinline__ ull pack2f(float lo, float hi) {
    ull d;
    asm("mov.b64 %0, {%1, %2};" : "=l"(d) : "f"(lo), "f"(hi));
    return d;
}
__device__ __forceinline__ void unpack2f(ull v, float& lo, float& hi) {
    asm("mov.b64 {%0, %1}, %2;" : "=f"(lo), "=f"(hi) : "l"(v));
}
__device__ __forceinline__ uint32_t packh(float v0, float v1) {
    uint32_t r;
    asm("cvt.rn.f16x2.f32 %0, %1, %2;" : "=r"(r) : "f"(v1), "f"(v0));
    return r;
}
// packed f32x2 -> fp16x2 (low lane -> low half)
__device__ __forceinline__ uint32_t cvt2h(ull v) {
    float lo, hi;
    unpack2f(v, lo, hi);
    return packh(lo, hi);
}

// packed sin for |x| <= pi/2 (5-term odd minimax; relatively exact small x)
__device__ __forceinline__ ull sin2_small(ull x) {
    const ull C3 = pack2f(-1.6666667e-1f, -1.6666667e-1f);
    const ull C5 = pack2f( 8.3333310e-3f,  8.3333310e-3f);
    const ull C7 = pack2f(-1.9841271e-4f, -1.9841271e-4f);
    const ull C9 = pack2f( 2.7557314e-6f,  2.7557314e-6f);
    ull x2 = mul2(x, x);
    ull x3 = mul2(x2, x);
    ull p = fma2(C9, x2, C7);
    p = fma2(p, x2, C5);
    p = fma2(p, x2, C3);
    return fma2(p, x3, x);
}

// packed accurate sin for |z| <= ~32: magic-number rint + Cody-Waite by pi,
// per-lane sign flip from the parity bit of the magic-biased mantissa.
__device__ __forceinline__ ull sin2_cw(ull z) {
    const ull INVPI = pack2f(0.318309886183790672f, 0.318309886183790672f);
    const ull MAG   = pack2f(12582912.0f, 12582912.0f);     // 2^23 + 2^22
    const ull NMAG  = pack2f(-12582912.0f, -12582912.0f);
    const ull NPIH  = pack2f(-3.14159274101257324f, -3.14159274101257324f);
    const ull PILO  = pack2f(8.74227800296169792e-8f, 8.74227800296169792e-8f);
    ull t = fma2(z, INVPI, MAG);                  // k (round-even) in mantissa
    ull sgn = ((t & 1ull) << 31) | (((t >> 32) & 1ull) << 63);
    ull k = add2(t, NMAG);                        // k as float pair
    ull r = fma2(k, NPIH, z);
    r = fma2(k, PILO, r);
    return sin2_small(r) ^ sgn;
}

// ---- prep: W[L] fp32 [256][256] -> fp16 chunk-contiguous layout ----
__global__ void siren_prep_kernel(const float* __restrict__ W1,
                                  const float* __restrict__ W2,
                                  const float* __restrict__ W3) {
    int idx = blockIdx.x * blockDim.x + threadIdx.x;
    if (idx >= 3 * 256 * 128) return;
    int L = idx / (256 * 128);
    int r = idx % (256 * 128);
    int n = r / 128;
    int k = (r % 128) * 2;
    const float* W = (L == 0) ? W1 : (L == 1) ? W2 : W3;
    float v0 = __ldg(W + n * HID + k);
    float v1 = __ldg(W + n * HID + k + 1);
    unsigned char* dst = g_prepW + L * PREP_L + (k >> 5) * PREP_C
                       + n * BROWB + (k & 31) * 2;
    *(uint32_t*)dst = packh(v0, v1);
}

__global__ void __launch_bounds__(NTHREADS, 2) siren_mma_kernel(
    const float* __restrict__ x,
    const float* __restrict__ W0, const float* __restrict__ b0,
    const float* __restrict__ b1, const float* __restrict__ b2,
    const float* __restrict__ b3,
    const float* __restrict__ W4, const float* __restrict__ b4,
    float* __restrict__ out, int npts)
{
    extern __shared__ char smem[];
    const uint32_t sb = smem_u32(smem);
    const int tid = threadIdx.x;
    const int w = tid >> 5, l = tid & 31;
    const int mw = w & 1, nw = w >> 1;       // 2 M-groups x 4 N-groups
    const int tile0 = blockIdx.x * PTILE;

    float* xs = (float*)(smem + OFF_XS);
    float* psum = (float*)(smem + OFF_PSUM);

    const uint32_t stDst = sb + OFF_B + (uint32_t)(tid * 16);

    if (tid < PTILE * 3) {
        int idx = tile0 * 3 + tid;
        xs[tid] = (idx < npts * 3) ? x[idx] : 0.0f;
    }

    // prefetch layer-1 weights chunk 0 while layer 0 computes
    {
        const unsigned char* src = g_prepW + tid * 16;
#pragma unroll
        for (int i = 0; i < 5; i++)
            cpa16(stDst + i * 4096, src + i * 4096);
        CP_COMMIT();
    }
    __syncthreads();

    // ---- layer 0: a0 = sin(30*(W0 x + b0)) -> A fp16 ----
    // warp-uniform weight loads: all lanes of a warp share nb
    {
        int p = tid & 63;
        int nb = (tid >> 6) * 64;
        float x0 = xs[p * 3], x1 = xs[p * 3 + 1], x2 = xs[p * 3 + 2];
        char* ar = smem + p * AROWB;
#pragma unroll 8
        for (int j = 0; j < 64; j += 2) {
            int n = nb + j;
            float za = 30.0f * fmaf(__ldg(W0 + n * 3), x0,
                           fmaf(__ldg(W0 + n * 3 + 1), x1,
                           fmaf(__ldg(W0 + n * 3 + 2), x2, __ldg(b0 + n))));
            float zb = 30.0f * fmaf(__ldg(W0 + n * 3 + 3), x0,
                           fmaf(__ldg(W0 + n * 3 + 4), x1,
                           fmaf(__ldg(W0 + n * 3 + 5), x2, __ldg(b0 + n + 1))));
            *(uint32_t*)(ar + n * 2) = cvt2h(sin2_cw(pack2f(za, zb)));
        }
    }

    // ---- ldmatrix per-lane addresses ----
    const int lt = l >> 3, l7 = l & 7;
    const uint32_t aBase = sb + (uint32_t)((mw * 32 + l7 + ((lt & 1) << 3)) * AROWB
                                           + (((lt >> 1) << 3) * 2));
    const uint32_t bBase = sb + OFF_B
        + (uint32_t)((nw * 64 + l7 + ((lt >> 1) << 3)) * BROWB
                     + (((lt & 1) << 3) * 2));

    // activation scaling: a_L = h_L * S[L];  epilogue: z = y*invS + b
    const float invS[3] = {1.0f, 1.0f / 16.0f, 1.0f / 512.0f};
    const float Sout[2] = {16.0f, 512.0f};

#pragma unroll 1
    for (int L = 0; L < 3; L++) {
        const float* bb = (L == 0) ? b1 : (L == 1) ? b2 : b3;
        const ull is2 = pack2f(invS[L], invS[L]);

        float acc[2][8][4];
#pragma unroll
        for (int mt = 0; mt < 2; mt++)
#pragma unroll
            for (int nt = 0; nt < 8; nt++)
#pragma unroll
                for (int q = 0; q < 4; q++) acc[mt][nt][q] = 0.0f;

#pragma unroll 1
        for (int c = 0; c < NCHUNK; c++) {
            const int t = L * NCHUNK + c;
            CP_WAIT0();
            __syncthreads();   // chunk t staged; chunk t-1 MMAs done

            if (t + 1 < NT_TOTAL) {
                const unsigned char* src = g_prepW + (t + 1) * PREP_C + tid * 16;
                uint32_t dst = stDst + (uint32_t)(((t + 1) & 1) * B_BUF);
#pragma unroll
                for (int i = 0; i < 5; i++)
                    cpa16(dst + i * 4096, src + i * 4096);
                CP_COMMIT();
            }

            const uint32_t bufB = bBase + (uint32_t)((t & 1) * B_BUF);
#pragma unroll
            for (int s = 0; s < 2; s++) {
                const int kk = c * 2 + s;
                uint32_t af[2][4];
                ldsm4(af[0], aBase + kk * 32);
                ldsm4(af[1], aBase + 16 * AROWB + kk * 32);
#pragma unroll
                for (int np = 0; np < 4; np++) {
                    uint32_t bf[4];
                    ldsm4(bf, bufB + np * 16 * BROWB + s * 32);
                    mma16816(acc[0][2 * np],     af[0], bf[0], bf[1]);
                    mma16816(acc[1][2 * np],     af[1], bf[0], bf[1]);
                    mma16816(acc[0][2 * np + 1], af[0], bf[2], bf[3]);
                    mma16816(acc[1][2 * np + 1], af[1], bf[2], bf[3]);
                }
            }
        }
        __syncthreads();   // all MMAs done before A is overwritten

        if (L < 2) {
            // epilogue (packed): a = sin(y*invS + b) * Sout -> A fp16 in place
            const ull so2 = pack2f(Sout[L], Sout[L]);
#pragma unroll
            for (int mt = 0; mt < 2; mt++) {
                int pr = mw * 32 + mt * 16 + (l >> 2);
#pragma unroll
                for (int nt = 0; nt < 8; nt++) {
                    int nc = nw * 64 + nt * 8 + (l & 3) * 2;
                    float2 bp = __ldg(reinterpret_cast<const float2*>(bb + nc));
                    ull b2p = pack2f(bp.x, bp.y);
                    ull z01 = fma2(pack2f(acc[mt][nt][0], acc[mt][nt][1]), is2, b2p);
                    ull z23 = fma2(pack2f(acc[mt][nt][2], acc[mt][nt][3]), is2, b2p);
                    uint32_t h01 = cvt2h(mul2(sin2_small(z01), so2));
                    uint32_t h23 = cvt2h(mul2(sin2_small(z23), so2));
                    *(uint32_t*)(smem + pr * AROWB + nc * 2)       = h01;
                    *(uint32_t*)(smem + (pr + 8) * AROWB + nc * 2) = h23;
                }
            }
            __syncthreads();
        } else {
            // final: h3 = sin(y*invS + b3) (packed); out_c partial dots scalar
            float part[2][2][3];
#pragma unroll
            for (int mt = 0; mt < 2; mt++)
#pragma unroll
                for (int rh = 0; rh < 2; rh++)
#pragma unroll
                    for (int cc = 0; cc < 3; cc++) part[mt][rh][cc] = 0.0f;

#pragma unroll
            for (int mt = 0; mt < 2; mt++)
#pragma unroll
            for (int nt = 0; nt < 8; nt++) {
                int nc = nw * 64 + nt * 8 + (l & 3) * 2;
                float2 bp = __ldg(reinterpret_cast<const float2*>(bb + nc));
                ull b2p = pack2f(bp.x, bp.y);
                ull z01 = fma2(pack2f(acc[mt][nt][0], acc[mt][nt][1]), is2, b2p);
                ull z23 = fma2(pack2f(acc[mt][nt][2], acc[mt][nt][3]), is2, b2p);
                float h0, h1, h2, h3v;
                unpack2f(sin2_small(z01), h0, h1);
                unpack2f(sin2_small(z23), h2, h3v);
#pragma unroll
                for (int cc = 0; cc < 3; cc++) {
                    float2 wp = __ldg(reinterpret_cast<const float2*>(
                        W4 + cc * HID + nc));
                    part[mt][0][cc] = fmaf(wp.x, h0, fmaf(wp.y, h1, part[mt][0][cc]));
                    part[mt][1][cc] = fmaf(wp.x, h2, fmaf(wp.y, h3v, part[mt][1][cc]));
                }
            }
#pragma unroll
            for (int mt = 0; mt < 2; mt++)
#pragma unroll
            for (int rh = 0; rh < 2; rh++)
#pragma unroll
            for (int cc = 0; cc < 3; cc++) {
                float v = part[mt][rh][cc];
                v += __shfl_xor_sync(0xffffffffu, v, 1);
                v += __shfl_xor_sync(0xffffffffu, v, 2);
                part[mt][rh][cc] = v;
            }
            if ((l & 3) == 0) {
#pragma unroll
                for (int mt = 0; mt < 2; mt++)
#pragma unroll
                for (int rh = 0; rh < 2; rh++) {
                    int p = mw * 32 + mt * 16 + rh * 8 + (l >> 2);
#pragma unroll
                    for (int cc = 0; cc < 3; cc++)
                        psum[nw * 192 + p * 3 + cc] = part[mt][rh][cc];
                }
            }
        }
    }

    __syncthreads();
    if (tid < PTILE * 3) {
        float v = psum[tid] + psum[192 + tid] + psum[384 + tid]
                + psum[576 + tid] + __ldg(b4 + tid % 3);
        int idx = tile0 * 3 + tid;
        if (idx < npts * 3) out[idx] = v;
    }
}

extern "C" void kernel_launch(void* const* d_in, const int* in_sizes, int n_in,
                              void* d_out, int out_size) {
    const float* x  = (const float*)d_in[0];
    const float* W0 = (const float*)d_in[1];
    const float* b0 = (const float*)d_in[2];
    const float* W1 = (const float*)d_in[3];
    const float* b1 = (const float*)d_in[4];
    const float* W2 = (const float*)d_in[5];
    const float* b2 = (const float*)d_in[6];
    const float* W3 = (const float*)d_in[7];
    const float* b3 = (const float*)d_in[8];
    const float* W4 = (const float*)d_in[9];
    const float* b4 = (const float*)d_in[10];
    float* out = (float*)d_out;

    int npts = in_sizes[0] / 3;
    int nblocks = (npts + PTILE - 1) / PTILE;

    siren_prep_kernel<<<384, 256>>>(W1, W2, W3);

    cudaFuncSetAttribute(siren_mma_kernel,
                         cudaFuncAttributeMaxDynamicSharedMemorySize, SMEM_SZ);
    siren_mma_kernel<<<nblocks, NTHREADS, SMEM_SZ>>>(
        x, W0, b0, b1, b2, b3, W4, b4, out, npts);
}

// round 15
// speedup vs baseline: 8.4910x; 1.0728x over previous
#include <cuda_runtime.h>
#include <cuda_bf16.h>
#include <cstdint>

// Fused SIREN MLP via single-product fp16 HMMA: 3 -> 256 -> 256 -> 256 -> 256 -> 3
// Round 14: block-wide chunk barriers replaced by small-group named barriers.
//  - B staged per nw-pair (2 warps sharing 64 neuron rows): private double
//    buffer, flat coalesced cp.async copy, bar.sync(1+nw, 64) per chunk.
//  - A epilogue fenced by bar.sync(5+mw, 128) (the 4 warps sharing 32 rows).
//  - only 3 block-wide __syncthreads remain (xs, layer0-A, psum).
// Rest identical to R13: PTILE=64, 256 thr, 2 CTAs/SM, prep kernel converts
// weights fp32->fp16 into the exact smem layout, packed-f32x2 sin epilogues,
// static activation scaling S = {1,16,512}.

#define NTHREADS 256
#define PTILE 64
#define HID 256
#define NCHUNK 8
#define AROWB 528
#define BROWB 80

#define OFF_B    33792
#define BG       5120      // one buf for one nw-group: 64 rows x 80B
#define OFF_PSUM 74752
#define OFF_XS   77824
#define SMEM_SZ  78592

#define PREP_C   20480
#define NT_TOTAL 24

typedef unsigned long long ull;

__device__ __align__(16) unsigned char g_prepW[3 * 8 * PREP_C];

__device__ __forceinline__ uint32_t smem_u32(const void* p) {
    uint32_t a;
    asm("{ .reg .u64 t; cvta.to.shared.u64 t, %1; cvt.u32.u64 %0, t; }"
        : "=r"(a) : "l"(p));
    return a;
}

#define BAR_SYNC(id, n) \
    asm volatile("bar.sync %0, %1;" :: "r"(id), "r"(n) : "memory")

__device__ __forceinline__ void ldsm4(uint32_t a[4], uint32_t addr) {
    asm volatile("ldmatrix.sync.aligned.m8n8.x4.shared.b16 {%0,%1,%2,%3}, [%4];"
                 : "=r"(a[0]), "=r"(a[1]), "=r"(a[2]), "=r"(a[3]) : "r"(addr));
}

__device__ __forceinline__ void mma16816(float d[4], const uint32_t a[4],
                                         uint32_t b0, uint32_t b1) {
    asm volatile("mma.sync.aligned.m16n8k16.row.col.f32.f16.f16.f32 "
                 "{%0,%1,%2,%3}, {%4,%5,%6,%7}, {%8,%9}, {%0,%1,%2,%3};"
                 : "+f"(d[0]), "+f"(d[1]), "+f"(d[2]), "+f"(d[3])
                 : "r"(a[0]), "r"(a[1]), "r"(a[2]), "r"(a[3]),
                   "r"(b0), "r"(b1));
}

__device__ __forceinline__ void cpa16(uint32_t dst, const void* src) {
    asm volatile("cp.async.cg.shared.global [%0], [%1], 16;"
                 :: "r"(dst), "l"(src) : "memory");
}
#define CP_COMMIT() asm volatile("cp.async.commit_group;" ::: "memory")
#define CP_WAIT0()  asm volatile("cp.async.wait_group 0;" ::: "memory")

// ---------------- packed f32x2 helpers ----------------
__device__ __forceinline__ ull fma2(ull a, ull b, ull c) {
    ull d;
    asm("fma.rn.f32x2 %0, %1, %2, %3;" : "=l"(d) : "l"(a), "l"(b), "l"(c));
    return d;
}
__device__ __forceinline__ ull mul2(ull a, ull b) {
    ull d;
    asm("mul.rn.f32x2 %0, %1, %2;" : "=l"(d) : "l"(a), "l"(b));
    return d;
}
__device__ __forceinline__ ull add2(ull a, ull b) {
    ull d;
    asm("add.rn.f32x2 %0, %1, %2;" : "=l"(d) : "l"(a), "l"(b));
    return d;
}
__device__ __forceinline__ ull pack2f(float lo, float hi) {
    ull d;
    asm("mov.b64 %0, {%1, %2};" : "=l"(d) : "f"(lo), "f"(hi));
    return d;
}
__device__ __forceinline__ void unpack2f(ull v, float& lo, float& hi) {
    asm("mov.b64 {%0, %1}, %2;" : "=f"(lo), "=f"(hi) : "l"(v));
}
__device__ __forceinline__ uint32_t packh(float v0, float v1) {
    uint32_t r;
    asm("cvt.rn.f16x2.f32 %0, %1, %2;" : "=r"(r) : "f"(v1), "f"(v0));
    return r;
}
__device__ __forceinline__ uint32_t cvt2h(ull v) {
    float lo, hi;
    unpack2f(v, lo, hi);
    return packh(lo, hi);
}

// packed sin for |x| <= pi/2
__device__ __forceinline__ ull sin2_small(ull x) {
    const ull C3 = pack2f(-1.6666667e-1f, -1.6666667e-1f);
    const ull C5 = pack2f( 8.3333310e-3f,  8.3333310e-3f);
    const ull C7 = pack2f(-1.9841271e-4f, -1.9841271e-4f);
    const ull C9 = pack2f( 2.7557314e-6f,  2.7557314e-6f);
    ull x2 = mul2(x, x);
    ull x3 = mul2(x2, x);
    ull p = fma2(C9, x2, C7);
    p = fma2(p, x2, C5);
    p = fma2(p, x2, C3);
    return fma2(p, x3, x);
}

// packed accurate sin for |z| <= ~32 (magic-number rint + Cody-Waite by pi)
__device__ __forceinline__ ull sin2_cw(ull z) {
    const ull INVPI = pack2f(0.318309886183790672f, 0.318309886183790672f);
    const ull MAG   = pack2f(12582912.0f, 12582912.0f);
    const ull NMAG  = pack2f(-12582912.0f, -12582912.0f);
    const ull NPIH  = pack2f(-3.14159274101257324f, -3.14159274101257324f);
    const ull PILO  = pack2f(8.74227800296169792e-8f, 8.74227800296169792e-8f);
    ull t = fma2(z, INVPI, MAG);
    ull sgn = ((t & 1ull) << 31) | (((t >> 32) & 1ull) << 63);
    ull k = add2(t, NMAG);
    ull r = fma2(k, NPIH, z);
    r = fma2(k, PILO, r);
    return sin2_small(r) ^ sgn;
}

// ---- prep: W[L] fp32 [256][256] -> fp16 chunk-contiguous layout ----
__global__ void siren_prep_kernel(const float* __restrict__ W1,
                                  const float* __restrict__ W2,
                                  const float* __restrict__ W3) {
    int idx = blockIdx.x * blockDim.x + threadIdx.x;
    if (idx >= 3 * 256 * 128) return;
    int L = idx / (256 * 128);
    int r = idx % (256 * 128);
    int n = r / 128;
    int k = (r % 128) * 2;
    const float* W = (L == 0) ? W1 : (L == 1) ? W2 : W3;
    float v0 = __ldg(W + n * HID + k);
    float v1 = __ldg(W + n * HID + k + 1);
    unsigned char* dst = g_prepW + (L * 8 + (k >> 5)) * PREP_C
                       + n * BROWB + (k & 31) * 2;
    *(uint32_t*)dst = packh(v0, v1);
}

__global__ void __launch_bounds__(NTHREADS, 2) siren_mma_kernel(
    const float* __restrict__ x,
    const float* __restrict__ W0, const float* __restrict__ b0,
    const float* __restrict__ b1, const float* __restrict__ b2,
    const float* __restrict__ b3,
    const float* __restrict__ W4, const float* __restrict__ b4,
    float* __restrict__ out, int npts)
{
    extern __shared__ char smem[];
    const uint32_t sb = smem_u32(smem);
    const int tid = threadIdx.x;
    const int w = tid >> 5, l = tid & 31;
    const int mw = w & 1, nw = w >> 1;       // 2 M-groups x 4 N-groups
    const int tile0 = blockIdx.x * PTILE;

    float* xs = (float*)(smem + OFF_XS);
    float* psum = (float*)(smem + OFF_PSUM);

    // per-warp staging base: nw-group region (2 bufs), this warp's half rows
    const uint32_t stBase = sb + OFF_B + (uint32_t)(nw * 2 * BG + mw * 2560
                                                    + l * 16);
    const uint32_t prepWoff = (uint32_t)(nw * BG + mw * 2560 + l * 16);

    if (tid < PTILE * 3) {
        int idx = tile0 * 3 + tid;
        xs[tid] = (idx < npts * 3) ? x[idx] : 0.0f;
    }

    // prefetch layer-1 chunk 0 (this pair's 64 rows) while layer 0 computes
    {
        const unsigned char* src = g_prepW + prepWoff;
#pragma unroll
        for (int i = 0; i < 5; i++)
            cpa16(stBase + i * 512, src + i * 512);
        CP_COMMIT();
    }
    __syncthreads();                         // xs visible

    // ---- layer 0: a0 = sin(30*(W0 x + b0)) -> A fp16 (warp-uniform LDGs) ----
    {
        int p = tid & 63;
        int nb = (tid >> 6) * 64;
        float x0 = xs[p * 3], x1 = xs[p * 3 + 1], x2 = xs[p * 3 + 2];
        char* ar = smem + p * AROWB;
#pragma unroll 8
        for (int j = 0; j < 64; j += 2) {
            int n = nb + j;
            float za = 30.0f * fmaf(__ldg(W0 + n * 3), x0,
                           fmaf(__ldg(W0 + n * 3 + 1), x1,
                           fmaf(__ldg(W0 + n * 3 + 2), x2, __ldg(b0 + n))));
            float zb = 30.0f * fmaf(__ldg(W0 + n * 3 + 3), x0,
                           fmaf(__ldg(W0 + n * 3 + 4), x1,
                           fmaf(__ldg(W0 + n * 3 + 5), x2, __ldg(b0 + n + 1))));
            *(uint32_t*)(ar + n * 2) = cvt2h(sin2_cw(pack2f(za, zb)));
        }
    }
    __syncthreads();                         // layer-0 A visible to all

    // ---- ldmatrix per-lane addresses ----
    const int lt = l >> 3, l7 = l & 7;
    const uint32_t aBase = sb + (uint32_t)((mw * 32 + l7 + ((lt & 1) << 3)) * AROWB
                                           + (((lt >> 1) << 3) * 2));
    // B: within this nw-group's 64-row region
    const uint32_t bBase = sb + OFF_B + (uint32_t)(nw * 2 * BG
        + (l7 + ((lt >> 1) << 3)) * BROWB + (((lt & 1) << 3) * 2));

    const float invS[3] = {1.0f, 1.0f / 16.0f, 1.0f / 512.0f};
    const float Sout[2] = {16.0f, 512.0f};
    const int barPair = 1 + nw;              // 64-thread pair barrier
    const int barM = 5 + mw;                 // 128-thread mw-group barrier

#pragma unroll 1
    for (int L = 0; L < 3; L++) {
        const float* bb = (L == 0) ? b1 : (L == 1) ? b2 : b3;
        const ull is2 = pack2f(invS[L], invS[L]);

        float acc[2][8][4];
#pragma unroll
        for (int mt = 0; mt < 2; mt++)
#pragma unroll
            for (int nt = 0; nt < 8; nt++)
#pragma unroll
                for (int q = 0; q < 4; q++) acc[mt][nt][q] = 0.0f;

#pragma unroll 1
        for (int c = 0; c < NCHUNK; c++) {
            const int t = L * NCHUNK + c;
            CP_WAIT0();
            BAR_SYNC(barPair, 64);           // pair: chunk t staged, buf free

            if (t + 1 < NT_TOTAL) {
                const unsigned char* src =
                    g_prepW + (t + 1) * PREP_C + prepWoff;
                uint32_t dst = stBase + (uint32_t)(((t + 1) & 1) * BG);
#pragma unroll
                for (int i = 0; i < 5; i++)
                    cpa16(dst + i * 512, src + i * 512);
                CP_COMMIT();
            }

            const uint32_t bufB = bBase + (uint32_t)((t & 1) * BG);
#pragma unroll
            for (int s = 0; s < 2; s++) {
                const int kk = c * 2 + s;
                uint32_t af[2][4];
                ldsm4(af[0], aBase + kk * 32);
                ldsm4(af[1], aBase + 16 * AROWB + kk * 32);
#pragma unroll
                for (int np = 0; np < 4; np++) {
                    uint32_t bf[4];
                    ldsm4(bf, bufB + np * 16 * BROWB + s * 32);
                    mma16816(acc[0][2 * np],     af[0], bf[0], bf[1]);
                    mma16816(acc[1][2 * np],     af[1], bf[0], bf[1]);
                    mma16816(acc[0][2 * np + 1], af[0], bf[2], bf[3]);
                    mma16816(acc[1][2 * np + 1], af[1], bf[2], bf[3]);
                }
            }
        }

        if (L < 2) {
            // mw-group fence: 4 warps sharing A rows done reading layer L
            BAR_SYNC(barM, 128);
            const ull so2 = pack2f(Sout[L], Sout[L]);
#pragma unroll
            for (int mt = 0; mt < 2; mt++) {
                int pr = mw * 32 + mt * 16 + (l >> 2);
#pragma unroll
                for (int nt = 0; nt < 8; nt++) {
                    int nc = nw * 64 + nt * 8 + (l & 3) * 2;
                    float2 bp = __ldg(reinterpret_cast<const float2*>(bb + nc));
                    ull b2p = pack2f(bp.x, bp.y);
                    ull z01 = fma2(pack2f(acc[mt][nt][0], acc[mt][nt][1]), is2, b2p);
                    ull z23 = fma2(pack2f(acc[mt][nt][2], acc[mt][nt][3]), is2, b2p);
                    uint32_t h01 = cvt2h(mul2(sin2_small(z01), so2));
                    uint32_t h23 = cvt2h(mul2(sin2_small(z23), so2));
                    *(uint32_t*)(smem + pr * AROWB + nc * 2)       = h01;
                    *(uint32_t*)(smem + (pr + 8) * AROWB + nc * 2) = h23;
                }
            }
            BAR_SYNC(barM, 128);             // A(L+1) visible to mw group
        } else {
            // final: h3 = sin(y*invS + b3) (packed); partial out dots
            float part[2][2][3];
#pragma unroll
            for (int mt = 0; mt < 2; mt++)
#pragma unroll
                for (int rh = 0; rh < 2; rh++)
#pragma unroll
                    for (int cc = 0; cc < 3; cc++) part[mt][rh][cc] = 0.0f;

#pragma unroll
            for (int mt = 0; mt < 2; mt++)
#pragma unroll
            for (int nt = 0; nt < 8; nt++) {
                int nc = nw * 64 + nt * 8 + (l & 3) * 2;
                float2 bp = __ldg(reinterpret_cast<const float2*>(bb + nc));
                ull b2p = pack2f(bp.x, bp.y);
                ull z01 = fma2(pack2f(acc[mt][nt][0], acc[mt][nt][1]), is2, b2p);
                ull z23 = fma2(pack2f(acc[mt][nt][2], acc[mt][nt][3]), is2, b2p);
                float h0, h1, h2, h3v;
                unpack2f(sin2_small(z01), h0, h1);
                unpack2f(sin2_small(z23), h2, h3v);
#pragma unroll
                for (int cc = 0; cc < 3; cc++) {
                    float2 wp = __ldg(reinterpret_cast<const float2*>(
                        W4 + cc * HID + nc));
                    part[mt][0][cc] = fmaf(wp.x, h0, fmaf(wp.y, h1, part[mt][0][cc]));
                    part[mt][1][cc] = fmaf(wp.x, h2, fmaf(wp.y, h3v, part[mt][1][cc]));
                }
            }
#pragma unroll
            for (int mt = 0; mt < 2; mt++)
#pragma unroll
            for (int rh = 0; rh < 2; rh++)
#pragma unroll
            for (int cc = 0; cc < 3; cc++) {
                float v = part[mt][rh][cc];
                v += __shfl_xor_sync(0xffffffffu, v, 1);
                v += __shfl_xor_sync(0xffffffffu, v, 2);
                part[mt][rh][cc] = v;
            }
            if ((l & 3) == 0) {
#pragma unroll
                for (int mt = 0; mt < 2; mt++)
#pragma unroll
                for (int rh = 0; rh < 2; rh++) {
                    int p = mw * 32 + mt * 16 + rh * 8 + (l >> 2);
#pragma unroll
                    for (int cc = 0; cc < 3; cc++)
                        psum[nw * 192 + p * 3 + cc] = part[mt][rh][cc];
                }
            }
        }
    }

    __syncthreads();
    if (tid < PTILE * 3) {
        float v = psum[tid] + psum[192 + tid] + psum[384 + tid]
                + psum[576 + tid] + __ldg(b4 + tid % 3);
        int idx = tile0 * 3 + tid;
        if (idx < npts * 3) out[idx] = v;
    }
}

extern "C" void kernel_launch(void* const* d_in, const int* in_sizes, int n_in,
                              void* d_out, int out_size) {
    const float* x  = (const float*)d_in[0];
    const float* W0 = (const float*)d_in[1];
    const float* b0 = (const float*)d_in[2];
    const float* W1 = (const float*)d_in[3];
    const float* b1 = (const float*)d_in[4];
    const float* W2 = (const float*)d_in[5];
    const float* b2 = (const float*)d_in[6];
    const float* W3 = (const float*)d_in[7];
    const float* b3 = (const float*)d_in[8];
    const float* W4 = (const float*)d_in[9];
    const float* b4 = (const float*)d_in[10];
    float* out = (float*)d_out;

    int npts = in_sizes[0] / 3;
    int nblocks = (npts + PTILE - 1) / PTILE;

    siren_prep_kernel<<<384, 256>>>(W1, W2, W3);

    cudaFuncSetAttribute(siren_mma_kernel,
                         cudaFuncAttributeMaxDynamicSharedMemorySize, SMEM_SZ);
    siren_mma_kernel<<<nblocks, NTHREADS, SMEM_SZ>>>(
        x, W0, b0, b1, b2, b3, W4, b4, out, npts);
}